// round 2
// baseline (speedup 1.0000x reference)
#include <cuda_runtime.h>
#include <math.h>
#include <stdint.h>

#define BATCH  2
#define SEQLEN 2048
#define DMODEL 768
#define DSTATE 16
#define MROWS  (BATCH * SEQLEN)          // 4096
#define KFLAT  (DMODEL * DSTATE)         // 12288

// ---------------- scratch (device globals; no allocation allowed) ----------
__device__ float g_delta[(size_t)MROWS * DMODEL];          // 12.6 MB
__device__ float g_Bt[(size_t)MROWS * DSTATE];             // 256 KB
__device__ float g_Ct[(size_t)MROWS * DSTATE];             // 256 KB
__device__ float g_flat[(size_t)MROWS * KFLAT];            // 201 MB

__device__ __forceinline__ float softplusf(float x) {
    if (x > 20.f) return x;
    return log1pf(__expf(x));
}

// ---------------------------------------------------------------------------
// NT GEMM: C[M,Nn] = A[M,K] * Bw[Nn,K]^T + bias[n], optional softplus.
// BM=128, BN=128, BK=8, 256 threads, 8x8 accumulators/thread, double-buffered.
// Requires M%128==0, Nn%128==0, K%8==0 (true for all uses here).
// ---------------------------------------------------------------------------
template <bool SP>
__global__ void __launch_bounds__(256)
gemm_nt(const float* __restrict__ A, const float* __restrict__ Bw,
        const float* __restrict__ bias, float* __restrict__ C,
        int M, int Nn, int K)
{
    constexpr int BM = 128, BN = 128, BK = 8;
    __shared__ float As[2][BK][BM];
    __shared__ float Bs[2][BK][BN];

    const int t  = threadIdx.x;
    const int bm = blockIdx.y * BM;
    const int bn = blockIdx.x * BN;

    // Tile loaders: 128 rows x 8 k = 256 float4 -> one per thread (A and B each)
    const int lrow = t >> 1;
    const int lkv  = (t & 1) * 4;
    const float* Ag = A  + (size_t)(bm + lrow) * K + lkv;
    const float* Bg = Bw + (size_t)(bn + lrow) * K + lkv;

    // compute mapping: 16 row-groups x 16 col-groups, each 8x8
    const int rg = t >> 4;      // rows rg*8 .. rg*8+7
    const int cg = t & 15;      // cols cg*8 .. cg*8+7

    float acc[8][8];
#pragma unroll
    for (int i = 0; i < 8; i++)
#pragma unroll
        for (int j = 0; j < 8; j++) acc[i][j] = 0.f;

    // prologue: stage 0
    {
        float4 av = *(const float4*)Ag;
        float4 bv = *(const float4*)Bg;
        As[0][lkv + 0][lrow] = av.x;
        As[0][lkv + 1][lrow] = av.y;
        As[0][lkv + 2][lrow] = av.z;
        As[0][lkv + 3][lrow] = av.w;
        Bs[0][lkv + 0][lrow] = bv.x;
        Bs[0][lkv + 1][lrow] = bv.y;
        Bs[0][lkv + 2][lrow] = bv.z;
        Bs[0][lkv + 3][lrow] = bv.w;
    }
    __syncthreads();

    const int nk = K / BK;
    for (int kt = 0; kt < nk; ++kt) {
        const int cur = kt & 1;
        float4 an, bn4;
        if (kt + 1 < nk) {
            an  = *(const float4*)(Ag + (size_t)(kt + 1) * BK);
            bn4 = *(const float4*)(Bg + (size_t)(kt + 1) * BK);
        }
#pragma unroll
        for (int k = 0; k < BK; k++) {
            float4 a0 = *(const float4*)&As[cur][k][rg * 8];
            float4 a1 = *(const float4*)&As[cur][k][rg * 8 + 4];
            float4 b0 = *(const float4*)&Bs[cur][k][cg * 8];
            float4 b1 = *(const float4*)&Bs[cur][k][cg * 8 + 4];
            float af[8] = {a0.x, a0.y, a0.z, a0.w, a1.x, a1.y, a1.z, a1.w};
            float bf[8] = {b0.x, b0.y, b0.z, b0.w, b1.x, b1.y, b1.z, b1.w};
#pragma unroll
            for (int i = 0; i < 8; i++)
#pragma unroll
                for (int j = 0; j < 8; j++)
                    acc[i][j] = fmaf(af[i], bf[j], acc[i][j]);
        }
        if (kt + 1 < nk) {
            const int nxt = cur ^ 1;
            As[nxt][lkv + 0][lrow] = an.x;
            As[nxt][lkv + 1][lrow] = an.y;
            As[nxt][lkv + 2][lrow] = an.z;
            As[nxt][lkv + 3][lrow] = an.w;
            Bs[nxt][lkv + 0][lrow] = bn4.x;
            Bs[nxt][lkv + 1][lrow] = bn4.y;
            Bs[nxt][lkv + 2][lrow] = bn4.z;
            Bs[nxt][lkv + 3][lrow] = bn4.w;
        }
        __syncthreads();
    }

    // epilogue
    const float4 bv0 = *(const float4*)&bias[bn + cg * 8];
    const float4 bv1 = *(const float4*)&bias[bn + cg * 8 + 4];
    const float bb[8] = {bv0.x, bv0.y, bv0.z, bv0.w, bv1.x, bv1.y, bv1.z, bv1.w};
#pragma unroll
    for (int i = 0; i < 8; i++) {
        const int r = bm + rg * 8 + i;
        float o[8];
#pragma unroll
        for (int j = 0; j < 8; j++) {
            o[j] = acc[i][j] + bb[j];
            if (SP) o[j] = softplusf(o[j]);
        }
        float4 v0 = {o[0], o[1], o[2], o[3]};
        float4 v1 = {o[4], o[5], o[6], o[7]};
        *(float4*)&C[(size_t)r * Nn + bn + cg * 8]     = v0;
        *(float4*)&C[(size_t)r * Nn + bn + cg * 8 + 4] = v1;
    }
}

// ---------------------------------------------------------------------------
// Bt / Ct: per-row (b,l) GEMV onto 16+16 outputs. One block per row.
// ---------------------------------------------------------------------------
__global__ void __launch_bounds__(256)
bc_kernel(const float* __restrict__ x, const float* __restrict__ WB,
          const float* __restrict__ WC, float* __restrict__ Bt,
          float* __restrict__ Ct)
{
    __shared__ float xs[DMODEL];
    const int row = blockIdx.x;              // 0..MROWS-1
    const int t = threadIdx.x;
    for (int i = t; i < DMODEL; i += 256)
        xs[i] = x[(size_t)row * DMODEL + i];
    __syncthreads();

    const int warp = t >> 5;
    const int lane = t & 31;
#pragma unroll
    for (int o = 0; o < 4; o++) {
        const int j = warp * 4 + o;          // 0..31
        const float* W = (j < DSTATE) ? (WB + (size_t)j * DMODEL)
                                      : (WC + (size_t)(j - DSTATE) * DMODEL);
        float s = 0.f;
#pragma unroll 4
        for (int k = lane; k < DMODEL; k += 32)
            s = fmaf(xs[k], W[k], s);
#pragma unroll
        for (int off = 16; off; off >>= 1)
            s += __shfl_xor_sync(0xffffffffu, s, off);
        if (lane == 0) {
            if (j < DSTATE) Bt[(size_t)row * DSTATE + j] = s;
            else            Ct[(size_t)row * DSTATE + (j - DSTATE)] = s;
        }
    }
}

// ---------------------------------------------------------------------------
// Selective scan: one thread per (b, d, n) chain, sequential over L.
// h = exp(-delta*lam)*h + delta*Bt ;  y = h*Ct -> flat[b,l,d*N+n]
// ---------------------------------------------------------------------------
__global__ void __launch_bounds__(128)
scan_kernel(const float* __restrict__ delta, const float* __restrict__ Btg,
            const float* __restrict__ Ctg, const float* __restrict__ loglam,
            float* __restrict__ yflat)
{
    const int tid = blockIdx.x * 128 + threadIdx.x;  // < BATCH*DMODEL*DSTATE
    const int b = tid / (DMODEL * DSTATE);
    const int r = tid % (DMODEL * DSTATE);
    const int d = r / DSTATE;
    const int n = r % DSTATE;

    const float lam = softplusf(loglam[d * DSTATE + n]);

    const float* dp = delta + (size_t)b * SEQLEN * DMODEL + d;
    const float* bp = Btg + (size_t)b * SEQLEN * DSTATE + n;
    const float* cp = Ctg + (size_t)b * SEQLEN * DSTATE + n;
    float* yp = yflat + (size_t)b * SEQLEN * KFLAT + r;

    float h = 0.f;
    for (int l = 0; l < SEQLEN; l++) {
        const float dl = __ldg(dp); dp += DMODEL;
        const float bt = __ldg(bp); bp += DSTATE;
        const float ct = __ldg(cp); cp += DSTATE;
        const float a = __expf(-dl * lam);
        h = fmaf(a, h, dl * bt);
        *yp = h * ct;
        yp += KFLAT;
    }
}

// ---------------------------------------------------------------------------
extern "C" void kernel_launch(void* const* d_in, const int* in_sizes, int n_in,
                              void* d_out, int out_size)
{
    const float* x        = (const float*)d_in[0];
    const float* loglam   = (const float*)d_in[1];
    const float* Wd       = (const float*)d_in[2];
    const float* bd       = (const float*)d_in[3];
    const float* WB       = (const float*)d_in[4];
    const float* WC       = (const float*)d_in[5];
    const float* Wout     = (const float*)d_in[6];
    const float* bout     = (const float*)d_in[7];
    float* out            = (float*)d_out;

    float *p_delta, *p_Bt, *p_Ct, *p_flat;
    cudaGetSymbolAddress((void**)&p_delta, g_delta);
    cudaGetSymbolAddress((void**)&p_Bt,    g_Bt);
    cudaGetSymbolAddress((void**)&p_Ct,    g_Ct);
    cudaGetSymbolAddress((void**)&p_flat,  g_flat);

    // 1. delta = softplus(x @ Wd^T + bd)   [4096 x 768]
    {
        dim3 grid(DMODEL / 128, MROWS / 128);
        gemm_nt<true><<<grid, 256>>>(x, Wd, bd, p_delta, MROWS, DMODEL, DMODEL);
    }
    // 2. Bt, Ct
    bc_kernel<<<MROWS, 256>>>(x, WB, WC, p_Bt, p_Ct);

    // 3. scan -> flat [4096 x 12288]
    scan_kernel<<<(BATCH * DMODEL * DSTATE) / 128, 128>>>(p_delta, p_Bt, p_Ct,
                                                          loglam, p_flat);

    // 4. out = flat @ Wout^T + bout   [4096 x 768]
    {
        dim3 grid(DMODEL / 128, MROWS / 128);
        gemm_nt<false><<<grid, 256>>>(p_flat, Wout, bout, out, MROWS, DMODEL, KFLAT);
    }
}

// round 4
// speedup vs baseline: 1.9368x; 1.9368x over previous
#include <cuda_runtime.h>
#include <cuda_bf16.h>
#include <math.h>
#include <stdint.h>

#define BATCH  2
#define SEQLEN 2048
#define DMODEL 768
#define DSTATE 16
#define MROWS  (BATCH * SEQLEN)          // 4096
#define KFLAT  (DMODEL * DSTATE)         // 12288

// ---------------- scratch (device globals; no allocation allowed) ----------
__device__ float g_delta[(size_t)MROWS * DMODEL];
__device__ float g_Bt[(size_t)MROWS * DSTATE];
__device__ float g_Ct[(size_t)MROWS * DSTATE];
__device__ __nv_bfloat16 g_xhi[(size_t)MROWS * DMODEL];
__device__ __nv_bfloat16 g_xlo[(size_t)MROWS * DMODEL];
__device__ __nv_bfloat16 g_Wdhi[(size_t)DMODEL * DMODEL];
__device__ __nv_bfloat16 g_Wdlo[(size_t)DMODEL * DMODEL];
__device__ __nv_bfloat16 g_Wouthi[(size_t)DMODEL * KFLAT];
__device__ __nv_bfloat16 g_Woutlo[(size_t)DMODEL * KFLAT];
__device__ __nv_bfloat16 g_flathi[(size_t)MROWS * KFLAT];
__device__ __nv_bfloat16 g_flatlo[(size_t)MROWS * KFLAT];

__device__ __forceinline__ float softplusf(float x) {
    if (x > 20.f) return x;
    return log1pf(__expf(x));
}

__device__ __forceinline__ uint32_t smem_u32(const void* p) {
    uint32_t a;
    asm("{ .reg .u64 t; cvta.to.shared.u64 t, %1; cvt.u32.u64 %0, t; }"
        : "=r"(a) : "l"(p));
    return a;
}

__device__ __forceinline__ void cp16(uint32_t dst, const void* src) {
    asm volatile("cp.async.cg.shared.global [%0], [%1], 16;"
                 :: "r"(dst), "l"(src) : "memory");
}

#define MMA16816(d, a0, a1, a2, a3, b0, b1)                                   \
    asm volatile(                                                             \
        "mma.sync.aligned.m16n8k16.row.col.f32.bf16.bf16.f32 "                \
        "{%0,%1,%2,%3},{%4,%5,%6,%7},{%8,%9},{%0,%1,%2,%3};"                  \
        : "+f"((d)[0]), "+f"((d)[1]), "+f"((d)[2]), "+f"((d)[3])              \
        : "r"(a0), "r"(a1), "r"(a2), "r"(a3), "r"(b0), "r"(b1))

#define LDSM4(r0, r1, r2, r3, addr)                                           \
    asm volatile("ldmatrix.sync.aligned.m8n8.x4.shared.b16 {%0,%1,%2,%3}, [%4];" \
                 : "=r"(r0), "=r"(r1), "=r"(r2), "=r"(r3) : "r"(addr))

#define LDSM2(r0, r1, addr)                                                   \
    asm volatile("ldmatrix.sync.aligned.m8n8.x2.shared.b16 {%0,%1}, [%2];"    \
                 : "=r"(r0), "=r"(r1) : "r"(addr))

// ---------------------------------------------------------------------------
// Tensor-core NT GEMM, fp32 emulated via bf16 hi/lo 3-term split.
// C[M,Nn] = A[M,K] * Bw[Nn,K]^T + bias, optional softplus.
// Tile 128x128, BK=32, 256 thr (8 warps, 4x2), warp tile 32x64 (m16n8k16).
// Stage layout (32 KB): Ahi(8K) Alo(8K) Bhi(8K) Blo(8K); 2 stages = 64 KB.
// Smem row = 64 B (32 bf16), chunk swizzle: ch = c ^ ((row>>1)&3).
// ---------------------------------------------------------------------------
template <bool SP>
__global__ void __launch_bounds__(256, 1)
tgemm(const __nv_bfloat16* __restrict__ Ahi, const __nv_bfloat16* __restrict__ Alo,
      const __nv_bfloat16* __restrict__ Bhi, const __nv_bfloat16* __restrict__ Blo,
      const float* __restrict__ bias, float* __restrict__ C, int Nn, int K)
{
    extern __shared__ char dsm[];
    const uint32_t sb = smem_u32(dsm);
    const int t = threadIdx.x, wid = t >> 5, lane = t & 31;
    const int bm = blockIdx.y * 128, bn = blockIdx.x * 128;

    const size_t rs = (size_t)K * 2;              // gmem row stride (bytes)
    const char* A0 = (const char*)Ahi + (size_t)bm * rs;
    const char* A1 = (const char*)Alo + (size_t)bm * rs;
    const char* B0 = (const char*)Bhi + (size_t)bn * rs;
    const char* B1 = (const char*)Blo + (size_t)bn * rs;
    const char* srcs[4] = {A0, A1, B0, B1};

    // loader mapping: row = t>>1, two 16B chunks at (t&1)*2 + {0,1}
    const int lrow = t >> 1;
    const int lc0  = (t & 1) * 2;
    const int lsw  = (lrow >> 1) & 3;

    const int nk = K / 32;

    // warp tile: wm in 0..3 (m 32), wn in 0..1 (n 64)
    const int wm = wid >> 1, wn = wid & 1;
    const int mbase = wm * 32, nbase = wn * 64;

    float acc[2][8][4];
#pragma unroll
    for (int i = 0; i < 2; i++)
#pragma unroll
        for (int j = 0; j < 8; j++)
#pragma unroll
            for (int q = 0; q < 4; q++) acc[i][j][q] = 0.f;

    // ---- prologue: stage 0 ----
    {
#pragma unroll
        for (int b = 0; b < 4; b++) {
            const char* src = srcs[b] + (size_t)lrow * rs + lc0 * 16;
            uint32_t drow = sb + b * 8192 + lrow * 64;
#pragma unroll
            for (int i = 0; i < 2; i++)
                cp16(drow + ((lc0 + i) ^ lsw) * 16, src + i * 16);
        }
        asm volatile("cp.async.commit_group;" ::: "memory");
    }

    for (int kt = 0; kt < nk; kt++) {
        const int s = kt & 1;
        if (kt + 1 < nk) {
            const uint32_t st = sb + (s ^ 1) * 32768;
            const size_t kb = (size_t)(kt + 1) * 64;
#pragma unroll
            for (int b = 0; b < 4; b++) {
                const char* src = srcs[b] + (size_t)lrow * rs + kb + lc0 * 16;
                uint32_t drow = st + b * 8192 + lrow * 64;
#pragma unroll
                for (int i = 0; i < 2; i++)
                    cp16(drow + ((lc0 + i) ^ lsw) * 16, src + i * 16);
            }
            asm volatile("cp.async.commit_group;" ::: "memory");
            asm volatile("cp.async.wait_group 1;" ::: "memory");
        } else {
            asm volatile("cp.async.wait_group 0;" ::: "memory");
        }
        __syncthreads();

        const uint32_t st = sb + s * 32768;
#pragma unroll
        for (int ks = 0; ks < 2; ks++) {
            // A fragments (hi & lo) for 2 m16 tiles
            uint32_t ah[2][4], al[2][4];
#pragma unroll
            for (int mt = 0; mt < 2; mt++) {
                const int arow = mbase + mt * 16 + (lane & 15);
                const int ac   = (ks * 2 + (lane >> 4)) ^ ((arow >> 1) & 3);
                const uint32_t aoff = arow * 64 + ac * 16;
                LDSM4(ah[mt][0], ah[mt][1], ah[mt][2], ah[mt][3], st + aoff);
                LDSM4(al[mt][0], al[mt][1], al[mt][2], al[mt][3],
                      st + 8192 + aoff);
            }
            // B fragments (hi & lo) for 8 n8 tiles
            uint32_t bh[8][2], bl[8][2];
#pragma unroll
            for (int nt = 0; nt < 8; nt++) {
                const int brow = nbase + nt * 8 + (lane & 7);
                const int bc   = (ks * 2 + ((lane >> 3) & 1)) ^ ((brow >> 1) & 3);
                const uint32_t boff = brow * 64 + bc * 16;
                LDSM2(bh[nt][0], bh[nt][1], st + 16384 + boff);
                LDSM2(bl[nt][0], bl[nt][1], st + 24576 + boff);
            }
#pragma unroll
            for (int mt = 0; mt < 2; mt++)
#pragma unroll
                for (int nt = 0; nt < 8; nt++) {
                    MMA16816(acc[mt][nt], ah[mt][0], ah[mt][1], ah[mt][2],
                             ah[mt][3], bh[nt][0], bh[nt][1]);
                    MMA16816(acc[mt][nt], ah[mt][0], ah[mt][1], ah[mt][2],
                             ah[mt][3], bl[nt][0], bl[nt][1]);
                    MMA16816(acc[mt][nt], al[mt][0], al[mt][1], al[mt][2],
                             al[mt][3], bh[nt][0], bh[nt][1]);
                }
        }
        __syncthreads();
    }

    // ---- epilogue ----
#pragma unroll
    for (int mt = 0; mt < 2; mt++) {
        const int r0 = bm + mbase + mt * 16 + (lane >> 2);
#pragma unroll
        for (int nt = 0; nt < 8; nt++) {
            const int col = bn + nbase + nt * 8 + (lane & 3) * 2;
            float2 v0, v1;
            v0.x = acc[mt][nt][0] + __ldg(&bias[col]);
            v0.y = acc[mt][nt][1] + __ldg(&bias[col + 1]);
            v1.x = acc[mt][nt][2] + __ldg(&bias[col]);
            v1.y = acc[mt][nt][3] + __ldg(&bias[col + 1]);
            if (SP) {
                v0.x = softplusf(v0.x); v0.y = softplusf(v0.y);
                v1.x = softplusf(v1.x); v1.y = softplusf(v1.y);
            }
            *(float2*)&C[(size_t)r0 * Nn + col]       = v0;
            *(float2*)&C[(size_t)(r0 + 8) * Nn + col] = v1;
        }
    }
}

#define TG_SMEM 65536

// ---------------------------------------------------------------------------
// fp32 -> bf16 hi/lo split
// ---------------------------------------------------------------------------
__global__ void __launch_bounds__(256)
split_kernel(const float* __restrict__ in, __nv_bfloat16* __restrict__ hi,
             __nv_bfloat16* __restrict__ lo, int n)
{
    int i = blockIdx.x * 256 + threadIdx.x;
    if (i < n) {
        float v = in[i];
        __nv_bfloat16 h = __float2bfloat16(v);
        hi[i] = h;
        lo[i] = __float2bfloat16(v - __bfloat162float(h));
    }
}

// ---------------------------------------------------------------------------
// Bt / Ct: per-row GEMV onto 16+16 outputs. One block per row.
// ---------------------------------------------------------------------------
__global__ void __launch_bounds__(256)
bc_kernel(const float* __restrict__ x, const float* __restrict__ WB,
          const float* __restrict__ WC, float* __restrict__ Bt,
          float* __restrict__ Ct)
{
    __shared__ float xs[DMODEL];
    const int row = blockIdx.x;
    const int t = threadIdx.x;
    for (int i = t; i < DMODEL; i += 256)
        xs[i] = x[(size_t)row * DMODEL + i];
    __syncthreads();

    const int warp = t >> 5;
    const int lane = t & 31;
#pragma unroll
    for (int o = 0; o < 4; o++) {
        const int j = warp * 4 + o;
        const float* W = (j < DSTATE) ? (WB + (size_t)j * DMODEL)
                                      : (WC + (size_t)(j - DSTATE) * DMODEL);
        float s = 0.f;
#pragma unroll 4
        for (int k = lane; k < DMODEL; k += 32)
            s = fmaf(xs[k], W[k], s);
#pragma unroll
        for (int off = 16; off; off >>= 1)
            s += __shfl_xor_sync(0xffffffffu, s, off);
        if (lane == 0) {
            if (j < DSTATE) Bt[(size_t)row * DSTATE + j] = s;
            else            Ct[(size_t)row * DSTATE + (j - DSTATE)] = s;
        }
    }
}

// ---------------------------------------------------------------------------
// Selective scan: one thread per (b,d,n) chain; emits flat as bf16 hi/lo.
// ---------------------------------------------------------------------------
__global__ void __launch_bounds__(128)
scan_kernel(const float* __restrict__ delta, const float* __restrict__ Btg,
            const float* __restrict__ Ctg, const float* __restrict__ loglam,
            __nv_bfloat16* __restrict__ yhi, __nv_bfloat16* __restrict__ ylo)
{
    const int tid = blockIdx.x * 128 + threadIdx.x;
    const int b = tid / (DMODEL * DSTATE);
    const int r = tid % (DMODEL * DSTATE);
    const int d = r / DSTATE;
    const int n = r % DSTATE;

    const float lam = softplusf(loglam[d * DSTATE + n]);

    const float* dp = delta + (size_t)b * SEQLEN * DMODEL + d;
    const float* bp = Btg + (size_t)b * SEQLEN * DSTATE + n;
    const float* cp = Ctg + (size_t)b * SEQLEN * DSTATE + n;
    __nv_bfloat16* hp = yhi + (size_t)b * SEQLEN * KFLAT + r;
    __nv_bfloat16* lp = ylo + (size_t)b * SEQLEN * KFLAT + r;

    float h = 0.f;
    for (int l = 0; l < SEQLEN; l++) {
        const float dl = __ldg(dp); dp += DMODEL;
        const float bt = __ldg(bp); bp += DSTATE;
        const float ct = __ldg(cp); cp += DSTATE;
        const float a = __expf(-dl * lam);
        h = fmaf(a, h, dl * bt);
        const float y = h * ct;
        const __nv_bfloat16 hv = __float2bfloat16(y);
        *hp = hv;
        *lp = __float2bfloat16(y - __bfloat162float(hv));
        hp += KFLAT;
        lp += KFLAT;
    }
}

// ---------------------------------------------------------------------------
extern "C" void kernel_launch(void* const* d_in, const int* in_sizes, int n_in,
                              void* d_out, int out_size)
{
    const float* x      = (const float*)d_in[0];
    const float* loglam = (const float*)d_in[1];
    const float* Wd     = (const float*)d_in[2];
    const float* bd     = (const float*)d_in[3];
    const float* WB     = (const float*)d_in[4];
    const float* WC     = (const float*)d_in[5];
    const float* Wout   = (const float*)d_in[6];
    const float* bout   = (const float*)d_in[7];
    float* out          = (float*)d_out;

    float *p_delta, *p_Bt, *p_Ct;
    __nv_bfloat16 *p_xhi, *p_xlo, *p_Wdhi, *p_Wdlo, *p_Wouthi, *p_Woutlo,
                  *p_flathi, *p_flatlo;
    cudaGetSymbolAddress((void**)&p_delta,  g_delta);
    cudaGetSymbolAddress((void**)&p_Bt,     g_Bt);
    cudaGetSymbolAddress((void**)&p_Ct,     g_Ct);
    cudaGetSymbolAddress((void**)&p_xhi,    g_xhi);
    cudaGetSymbolAddress((void**)&p_xlo,    g_xlo);
    cudaGetSymbolAddress((void**)&p_Wdhi,   g_Wdhi);
    cudaGetSymbolAddress((void**)&p_Wdlo,   g_Wdlo);
    cudaGetSymbolAddress((void**)&p_Wouthi, g_Wouthi);
    cudaGetSymbolAddress((void**)&p_Woutlo, g_Woutlo);
    cudaGetSymbolAddress((void**)&p_flathi, g_flathi);
    cudaGetSymbolAddress((void**)&p_flatlo, g_flatlo);

    cudaFuncSetAttribute(tgemm<true>,  cudaFuncAttributeMaxDynamicSharedMemorySize, TG_SMEM);
    cudaFuncSetAttribute(tgemm<false>, cudaFuncAttributeMaxDynamicSharedMemorySize, TG_SMEM);

    // splits
    {
        int n1 = MROWS * DMODEL;
        split_kernel<<<(n1 + 255) / 256, 256>>>(x, p_xhi, p_xlo, n1);
        int n2 = DMODEL * DMODEL;
        split_kernel<<<(n2 + 255) / 256, 256>>>(Wd, p_Wdhi, p_Wdlo, n2);
        int n3 = DMODEL * KFLAT;
        split_kernel<<<(n3 + 255) / 256, 256>>>(Wout, p_Wouthi, p_Woutlo, n3);
    }

    // 1. delta = softplus(x @ Wd^T + bd)   [4096 x 768]
    tgemm<true><<<dim3(DMODEL / 128, MROWS / 128), 256, TG_SMEM>>>(
        p_xhi, p_xlo, p_Wdhi, p_Wdlo, bd, p_delta, DMODEL, DMODEL);

    // 2. Bt, Ct
    bc_kernel<<<MROWS, 256>>>(x, WB, WC, p_Bt, p_Ct);

    // 3. scan -> flat hi/lo [4096 x 12288]
    scan_kernel<<<(BATCH * DMODEL * DSTATE) / 128, 128>>>(
        p_delta, p_Bt, p_Ct, loglam, p_flathi, p_flatlo);

    // 4. out = flat @ Wout^T + bout   [4096 x 768]
    tgemm<false><<<dim3(DMODEL / 128, MROWS / 128), 256, TG_SMEM>>>(
        p_flathi, p_flatlo, p_Wouthi, p_Woutlo, bout, out, DMODEL, KFLAT);
}

// round 6
// speedup vs baseline: 2.9281x; 1.5119x over previous
#include <cuda_runtime.h>
#include <cuda_bf16.h>
#include <math.h>
#include <stdint.h>

#define BATCH  2
#define SEQLEN 2048
#define DMODEL 768
#define DSTATE 16
#define MROWS  (BATCH * SEQLEN)          // 4096
#define KFLAT  (DMODEL * DSTATE)         // 12288

// ---------------- scratch (device globals; no allocation allowed) ----------
__device__ float g_delta[(size_t)MROWS * DMODEL];
__device__ float g_Bt[(size_t)MROWS * DSTATE];
__device__ float g_Ct[(size_t)MROWS * DSTATE];
__device__ __nv_bfloat16 g_xhi[(size_t)MROWS * DMODEL];
__device__ __nv_bfloat16 g_xlo[(size_t)MROWS * DMODEL];
__device__ __nv_bfloat16 g_Wdhi[(size_t)DMODEL * DMODEL];
__device__ __nv_bfloat16 g_Wdlo[(size_t)DMODEL * DMODEL];
__device__ __nv_bfloat16 g_Wouthi[(size_t)DMODEL * KFLAT];
__device__ __nv_bfloat16 g_Woutlo[(size_t)DMODEL * KFLAT];
__device__ __nv_bfloat16 g_flathi[(size_t)MROWS * KFLAT];
__device__ __nv_bfloat16 g_flatlo[(size_t)MROWS * KFLAT];

__device__ __forceinline__ float softplusf(float x) {
    if (x > 20.f) return x;
    return log1pf(__expf(x));
}

__device__ __forceinline__ uint32_t smem_u32(const void* p) {
    uint32_t a;
    asm("{ .reg .u64 t; cvta.to.shared.u64 t, %1; cvt.u32.u64 %0, t; }"
        : "=r"(a) : "l"(p));
    return a;
}

__device__ __forceinline__ void cp16(uint32_t dst, const void* src) {
    asm volatile("cp.async.cg.shared.global [%0], [%1], 16;"
                 :: "r"(dst), "l"(src) : "memory");
}

#define MMA16816(d, a0, a1, a2, a3, b0, b1)                                   \
    asm volatile(                                                             \
        "mma.sync.aligned.m16n8k16.row.col.f32.bf16.bf16.f32 "                \
        "{%0,%1,%2,%3},{%4,%5,%6,%7},{%8,%9},{%0,%1,%2,%3};"                  \
        : "+f"((d)[0]), "+f"((d)[1]), "+f"((d)[2]), "+f"((d)[3])              \
        : "r"(a0), "r"(a1), "r"(a2), "r"(a3), "r"(b0), "r"(b1))

#define LDSM4(r0, r1, r2, r3, addr)                                           \
    asm volatile("ldmatrix.sync.aligned.m8n8.x4.shared.b16 {%0,%1,%2,%3}, [%4];" \
                 : "=r"(r0), "=r"(r1), "=r"(r2), "=r"(r3) : "r"(addr))

// ---------------------------------------------------------------------------
// Tensor-core NT GEMM, fp32 emulated via bf16 hi/lo 3-term split.
// C[M,Nn] = A[M,K]*Bw[Nn,K]^T + bias, optional softplus.
// BM=128, BN=192, BK=32, 4-stage cp.async, 256 thr (8 warps 2x4),
// warp tile 64x48. Smem row = 64 B (32 bf16); chunk swizzle c ^= (row>>1)&3.
// Stage: Ahi 8K | Alo 8K | Bhi 12K | Blo 12K = 40960 B. 4 stages = 160 KB.
// ---------------------------------------------------------------------------
#define BKB       64                 // BK bytes per row (32 bf16)
#define ST_AHI    0
#define ST_ALO    8192
#define ST_BHI    16384
#define ST_BLO    28672
#define ST_BYTES  40960
#define TG_SMEM   (4 * ST_BYTES)

template <bool SP>
__global__ void __launch_bounds__(256, 1)
tgemm(const __nv_bfloat16* __restrict__ Ahi, const __nv_bfloat16* __restrict__ Alo,
      const __nv_bfloat16* __restrict__ Bhi, const __nv_bfloat16* __restrict__ Blo,
      const float* __restrict__ bias, float* __restrict__ C, int Nn, int K)
{
    extern __shared__ char dsm[];
    const uint32_t sb = smem_u32(dsm);
    const int t = threadIdx.x, wid = t >> 5, lane = t & 31;
    const int bm = blockIdx.y * 128, bn = blockIdx.x * 192;

    const size_t rs = (size_t)K * 2;
    const char* A0 = (const char*)Ahi + (size_t)bm * rs;
    const char* A1 = (const char*)Alo + (size_t)bm * rs;
    const char* B0 = (const char*)Bhi + (size_t)bn * rs;
    const char* B1 = (const char*)Blo + (size_t)bn * rs;

    const int nk = K / 32;

    // loader mapping: 4 threads per 64B row, chunk = t&3
    const int lch  = t & 3;
    const int arow0 = t >> 2;            // + i*64, i=0..1  (128 rows)
    const int brow0 = t >> 2;            // + i*64, i=0..2  (192 rows)

    // warp tile: wm 0..1 (m64), wn 0..3 (n48)
    const int wm = wid >> 2, wn = wid & 3;
    const int mbase = wm * 64, nbase = wn * 48;

    float acc[4][6][4];
#pragma unroll
    for (int i = 0; i < 4; i++)
#pragma unroll
        for (int j = 0; j < 6; j++)
#pragma unroll
            for (int q = 0; q < 4; q++) acc[i][j][q] = 0.f;

    // ---- stage loader ----
    auto load_stage = [&](int kt) {
        const uint32_t st = sb + (kt & 3) * ST_BYTES;
        const size_t kb = (size_t)kt * BKB;
#pragma unroll
        for (int i = 0; i < 2; i++) {
            const int row = arow0 + i * 64;
            const uint32_t sw = (lch ^ ((row >> 1) & 3)) * 16;
            const size_t go = (size_t)row * rs + kb + lch * 16;
            cp16(st + ST_AHI + row * 64 + sw, A0 + go);
            cp16(st + ST_ALO + row * 64 + sw, A1 + go);
        }
#pragma unroll
        for (int i = 0; i < 3; i++) {
            const int row = brow0 + i * 64;
            const uint32_t sw = (lch ^ ((row >> 1) & 3)) * 16;
            const size_t go = (size_t)row * rs + kb + lch * 16;
            cp16(st + ST_BHI + row * 64 + sw, B0 + go);
            cp16(st + ST_BLO + row * 64 + sw, B1 + go);
        }
    };

    // prologue: stages 0..2
    for (int p = 0; p < 3; p++) {
        if (p < nk) load_stage(p);
        asm volatile("cp.async.commit_group;" ::: "memory");
    }

    for (int kt = 0; kt < nk; kt++) {
        asm volatile("cp.async.wait_group 2;" ::: "memory");
        __syncthreads();
        if (kt + 3 < nk) load_stage(kt + 3);
        asm volatile("cp.async.commit_group;" ::: "memory");

        const uint32_t st = sb + (kt & 3) * ST_BYTES;
#pragma unroll
        for (int ks = 0; ks < 2; ks++) {
            uint32_t ah[4][4], al[4][4];
#pragma unroll
            for (int mt = 0; mt < 4; mt++) {
                const int arow = mbase + mt * 16 + (lane & 15);
                const int ac = (ks * 2 + (lane >> 4)) ^ ((arow >> 1) & 3);
                const uint32_t off = arow * 64 + ac * 16;
                LDSM4(ah[mt][0], ah[mt][1], ah[mt][2], ah[mt][3],
                      st + ST_AHI + off);
                LDSM4(al[mt][0], al[mt][1], al[mt][2], al[mt][3],
                      st + ST_ALO + off);
            }
            uint32_t bh[6][2], bl[6][2];
#pragma unroll
            for (int p2 = 0; p2 < 3; p2++) {
                const int brow = nbase + p2 * 16 + ((lane >> 4) & 1) * 8 + (lane & 7);
                const int bc = (ks * 2 + ((lane >> 3) & 1)) ^ ((brow >> 1) & 3);
                const uint32_t off = brow * 64 + bc * 16;
                LDSM4(bh[p2 * 2][0], bh[p2 * 2][1], bh[p2 * 2 + 1][0],
                      bh[p2 * 2 + 1][1], st + ST_BHI + off);
                LDSM4(bl[p2 * 2][0], bl[p2 * 2][1], bl[p2 * 2 + 1][0],
                      bl[p2 * 2 + 1][1], st + ST_BLO + off);
            }
#pragma unroll
            for (int mt = 0; mt < 4; mt++)
#pragma unroll
                for (int nt = 0; nt < 6; nt++) {
                    MMA16816(acc[mt][nt], ah[mt][0], ah[mt][1], ah[mt][2],
                             ah[mt][3], bh[nt][0], bh[nt][1]);
                    MMA16816(acc[mt][nt], ah[mt][0], ah[mt][1], ah[mt][2],
                             ah[mt][3], bl[nt][0], bl[nt][1]);
                    MMA16816(acc[mt][nt], al[mt][0], al[mt][1], al[mt][2],
                             al[mt][3], bh[nt][0], bh[nt][1]);
                }
        }
        __syncthreads();
    }

    // ---- epilogue ----
#pragma unroll
    for (int mt = 0; mt < 4; mt++) {
        const int r0 = bm + mbase + mt * 16 + (lane >> 2);
#pragma unroll
        for (int nt = 0; nt < 6; nt++) {
            const int col = bn + nbase + nt * 8 + (lane & 3) * 2;
            const float b0 = __ldg(&bias[col]);
            const float b1 = __ldg(&bias[col + 1]);
            float2 v0, v1;
            v0.x = acc[mt][nt][0] + b0;
            v0.y = acc[mt][nt][1] + b1;
            v1.x = acc[mt][nt][2] + b0;
            v1.y = acc[mt][nt][3] + b1;
            if (SP) {
                v0.x = softplusf(v0.x); v0.y = softplusf(v0.y);
                v1.x = softplusf(v1.x); v1.y = softplusf(v1.y);
            }
            *(float2*)&C[(size_t)r0 * Nn + col]       = v0;
            *(float2*)&C[(size_t)(r0 + 8) * Nn + col] = v1;
        }
    }
}

// ---------------------------------------------------------------------------
// fp32 -> bf16 hi/lo split
// ---------------------------------------------------------------------------
__global__ void __launch_bounds__(256)
split_kernel(const float* __restrict__ in, __nv_bfloat16* __restrict__ hi,
             __nv_bfloat16* __restrict__ lo, int n)
{
    int i = blockIdx.x * 256 + threadIdx.x;
    if (i < n) {
        float v = in[i];
        __nv_bfloat16 h = __float2bfloat16(v);
        hi[i] = h;
        lo[i] = __float2bfloat16(v - __bfloat162float(h));
    }
}

// ---------------------------------------------------------------------------
// Bt / Ct: per-row GEMV onto 16+16 outputs. One block per row.
// ---------------------------------------------------------------------------
__global__ void __launch_bounds__(256)
bc_kernel(const float* __restrict__ x, const float* __restrict__ WB,
          const float* __restrict__ WC, float* __restrict__ Bt,
          float* __restrict__ Ct)
{
    __shared__ float xs[DMODEL];
    const int row = blockIdx.x;
    const int t = threadIdx.x;
    for (int i = t; i < DMODEL; i += 256)
        xs[i] = x[(size_t)row * DMODEL + i];
    __syncthreads();

    const int warp = t >> 5;
    const int lane = t & 31;
#pragma unroll
    for (int o = 0; o < 4; o++) {
        const int j = warp * 4 + o;
        const float* W = (j < DSTATE) ? (WB + (size_t)j * DMODEL)
                                      : (WC + (size_t)(j - DSTATE) * DMODEL);
        float s = 0.f;
#pragma unroll 4
        for (int k = lane; k < DMODEL; k += 32)
            s = fmaf(xs[k], W[k], s);
#pragma unroll
        for (int off = 16; off; off >>= 1)
            s += __shfl_xor_sync(0xffffffffu, s, off);
        if (lane == 0) {
            if (j < DSTATE) Bt[(size_t)row * DSTATE + j] = s;
            else            Ct[(size_t)row * DSTATE + (j - DSTATE)] = s;
        }
    }
}

// ---------------------------------------------------------------------------
// Selective scan: one thread per (b,d,n) chain; emits flat as bf16 hi/lo.
// ---------------------------------------------------------------------------
__global__ void __launch_bounds__(128)
scan_kernel(const float* __restrict__ delta, const float* __restrict__ Btg,
            const float* __restrict__ Ctg, const float* __restrict__ loglam,
            __nv_bfloat16* __restrict__ yhi, __nv_bfloat16* __restrict__ ylo)
{
    const int tid = blockIdx.x * 128 + threadIdx.x;
    const int b = tid / (DMODEL * DSTATE);
    const int r = tid % (DMODEL * DSTATE);
    const int d = r / DSTATE;
    const int n = r % DSTATE;

    const float lam = softplusf(loglam[d * DSTATE + n]);

    const float* dp = delta + (size_t)b * SEQLEN * DMODEL + d;
    const float* bp = Btg + (size_t)b * SEQLEN * DSTATE + n;
    const float* cp = Ctg + (size_t)b * SEQLEN * DSTATE + n;
    __nv_bfloat16* hp = yhi + (size_t)b * SEQLEN * KFLAT + r;
    __nv_bfloat16* lp = ylo + (size_t)b * SEQLEN * KFLAT + r;

    float h = 0.f;
    for (int l = 0; l < SEQLEN; l++) {
        const float dl = __ldg(dp); dp += DMODEL;
        const float bt = __ldg(bp); bp += DSTATE;
        const float ct = __ldg(cp); cp += DSTATE;
        const float a = __expf(-dl * lam);
        h = fmaf(a, h, dl * bt);
        const float y = h * ct;
        const __nv_bfloat16 hv = __float2bfloat16(y);
        *hp = hv;
        *lp = __float2bfloat16(y - __bfloat162float(hv));
        hp += KFLAT;
        lp += KFLAT;
    }
}

// ---------------------------------------------------------------------------
extern "C" void kernel_launch(void* const* d_in, const int* in_sizes, int n_in,
                              void* d_out, int out_size)
{
    const float* x      = (const float*)d_in[0];
    const float* loglam = (const float*)d_in[1];
    const float* Wd     = (const float*)d_in[2];
    const float* bd     = (const float*)d_in[3];
    const float* WB     = (const float*)d_in[4];
    const float* WC     = (const float*)d_in[5];
    const float* Wout   = (const float*)d_in[6];
    const float* bout   = (const float*)d_in[7];
    float* out          = (float*)d_out;

    float *p_delta, *p_Bt, *p_Ct;
    __nv_bfloat16 *p_xhi, *p_xlo, *p_Wdhi, *p_Wdlo, *p_Wouthi, *p_Woutlo,
                  *p_flathi, *p_flatlo;
    cudaGetSymbolAddress((void**)&p_delta,  g_delta);
    cudaGetSymbolAddress((void**)&p_Bt,     g_Bt);
    cudaGetSymbolAddress((void**)&p_Ct,     g_Ct);
    cudaGetSymbolAddress((void**)&p_xhi,    g_xhi);
    cudaGetSymbolAddress((void**)&p_xlo,    g_xlo);
    cudaGetSymbolAddress((void**)&p_Wdhi,   g_Wdhi);
    cudaGetSymbolAddress((void**)&p_Wdlo,   g_Wdlo);
    cudaGetSymbolAddress((void**)&p_Wouthi, g_Wouthi);
    cudaGetSymbolAddress((void**)&p_Woutlo, g_Woutlo);
    cudaGetSymbolAddress((void**)&p_flathi, g_flathi);
    cudaGetSymbolAddress((void**)&p_flatlo, g_flatlo);

    cudaFuncSetAttribute(tgemm<true>,  cudaFuncAttributeMaxDynamicSharedMemorySize, TG_SMEM);
    cudaFuncSetAttribute(tgemm<false>, cudaFuncAttributeMaxDynamicSharedMemorySize, TG_SMEM);

    // splits
    {
        int n1 = MROWS * DMODEL;
        split_kernel<<<(n1 + 255) / 256, 256>>>(x, p_xhi, p_xlo, n1);
        int n2 = DMODEL * DMODEL;
        split_kernel<<<(n2 + 255) / 256, 256>>>(Wd, p_Wdhi, p_Wdlo, n2);
        int n3 = DMODEL * KFLAT;
        split_kernel<<<(n3 + 255) / 256, 256>>>(Wout, p_Wouthi, p_Woutlo, n3);
    }

    // 1. delta = softplus(x @ Wd^T + bd)   [4096 x 768]
    tgemm<true><<<dim3(DMODEL / 192, MROWS / 128), 256, TG_SMEM>>>(
        p_xhi, p_xlo, p_Wdhi, p_Wdlo, bd, p_delta, DMODEL, DMODEL);

    // 2. Bt, Ct
    bc_kernel<<<MROWS, 256>>>(x, WB, WC, p_Bt, p_Ct);

    // 3. scan -> flat hi/lo [4096 x 12288]
    scan_kernel<<<(BATCH * DMODEL * DSTATE) / 128, 128>>>(
        p_delta, p_Bt, p_Ct, loglam, p_flathi, p_flatlo);

    // 4. out = flat @ Wout^T + bout   [4096 x 768]
    tgemm<false><<<dim3(DMODEL / 192, MROWS / 128), 256, TG_SMEM>>>(
        p_flathi, p_flatlo, p_Wouthi, p_Woutlo, bout, out, DMODEL, KFLAT);
}

// round 8
// speedup vs baseline: 2.9379x; 1.0033x over previous
#include <cuda_runtime.h>
#include <cuda_bf16.h>
#include <math.h>
#include <stdint.h>

#define BATCH  2
#define SEQLEN 2048
#define DMODEL 768
#define DSTATE 16
#define MROWS  (BATCH * SEQLEN)          // 4096
#define KFLAT  (DMODEL * DSTATE)         // 12288

// ---------------- scratch (device globals; no allocation allowed) ----------
__device__ float g_delta[(size_t)MROWS * DMODEL];
__device__ float g_Bt[(size_t)MROWS * DSTATE];
__device__ float g_Ct[(size_t)MROWS * DSTATE];
__device__ __nv_bfloat16 g_xhi[(size_t)MROWS * DMODEL];
__device__ __nv_bfloat16 g_xlo[(size_t)MROWS * DMODEL];
__device__ __nv_bfloat16 g_Wdhi[(size_t)DMODEL * DMODEL];
__device__ __nv_bfloat16 g_Wdlo[(size_t)DMODEL * DMODEL];
__device__ __nv_bfloat16 g_Wouthi[(size_t)DMODEL * KFLAT];
__device__ __nv_bfloat16 g_Woutlo[(size_t)DMODEL * KFLAT];
__device__ __nv_bfloat16 g_flathi[(size_t)MROWS * KFLAT];
__device__ __nv_bfloat16 g_flatlo[(size_t)MROWS * KFLAT];

__device__ __forceinline__ float softplusf(float x) {
    if (x > 20.f) return x;
    return log1pf(__expf(x));
}

__device__ __forceinline__ uint32_t smem_u32(const void* p) {
    uint32_t a;
    asm("{ .reg .u64 t; cvta.to.shared.u64 t, %1; cvt.u32.u64 %0, t; }"
        : "=r"(a) : "l"(p));
    return a;
}

__device__ __forceinline__ void cp16(uint32_t dst, const void* src) {
    asm volatile("cp.async.cg.shared.global [%0], [%1], 16;"
                 :: "r"(dst), "l"(src) : "memory");
}

#define MMA16816(d, a0, a1, a2, a3, b0, b1)                                   \
    asm volatile(                                                             \
        "mma.sync.aligned.m16n8k16.row.col.f32.bf16.bf16.f32 "                \
        "{%0,%1,%2,%3},{%4,%5,%6,%7},{%8,%9},{%0,%1,%2,%3};"                  \
        : "+f"((d)[0]), "+f"((d)[1]), "+f"((d)[2]), "+f"((d)[3])              \
        : "r"(a0), "r"(a1), "r"(a2), "r"(a3), "r"(b0), "r"(b1))

#define LDSM4(r0, r1, r2, r3, addr)                                           \
    asm volatile("ldmatrix.sync.aligned.m8n8.x4.shared.b16 {%0,%1,%2,%3}, [%4];" \
                 : "=r"(r0), "=r"(r1), "=r"(r2), "=r"(r3) : "r"(addr))

#define LDSM2(r0, r1, addr)                                                   \
    asm volatile("ldmatrix.sync.aligned.m8n8.x2.shared.b16 {%0,%1}, [%2];"    \
                 : "=r"(r0), "=r"(r1) : "r"(addr))

// ---------------------------------------------------------------------------
// Tensor-core NT GEMM, fp32 emulated via bf16 hi/lo 3-term split.
// C[M,Nn] = A[M,K]*Bw[Nn,K]^T + bias, optional softplus.
// BM=128, BN=96, BK=32, 3-stage cp.async, 256 thr (8 warps 2x4),
// warp tile 64x24, 2 CTAs/SM (grid 256 = one wave at occ 2).
// Smem row = 64 B; chunk swizzle c ^= (row>>1)&3.
// Stage: Ahi 8K | Alo 8K | Bhi 6K | Blo 6K = 28672 B. 3 stages = 86016 B.
// ---------------------------------------------------------------------------
#define BKB       64
#define ST_AHI    0
#define ST_ALO    8192
#define ST_BHI    16384
#define ST_BLO    22528
#define ST_BYTES  28672
#define TG_SMEM   (3 * ST_BYTES)

template <bool SP>
__global__ void __launch_bounds__(256, 2)
tgemm(const __nv_bfloat16* __restrict__ Ahi, const __nv_bfloat16* __restrict__ Alo,
      const __nv_bfloat16* __restrict__ Bhi, const __nv_bfloat16* __restrict__ Blo,
      const float* __restrict__ bias, float* __restrict__ C, int Nn, int K)
{
    extern __shared__ char dsm[];
    const uint32_t sb = smem_u32(dsm);
    const int t = threadIdx.x, wid = t >> 5, lane = t & 31;
    const int bm = blockIdx.y * 128, bn = blockIdx.x * 96;

    const size_t rs = (size_t)K * 2;
    const char* A0 = (const char*)Ahi + (size_t)bm * rs;
    const char* A1 = (const char*)Alo + (size_t)bm * rs;
    const char* B0 = (const char*)Bhi + (size_t)bn * rs;
    const char* B1 = (const char*)Blo + (size_t)bn * rs;

    const int nk = K / 32;

    // loader mapping: 4 threads per 64B row, chunk = t&3, row = t>>2
    const int lch  = t & 3;
    const int lrow = t >> 2;             // 0..63

    // warp tile: wm 0..1 (m64), wn 0..3 (n24)
    const int wm = wid >> 2, wn = wid & 3;
    const int mbase = wm * 64, nbase = wn * 24;

    float acc[4][3][4];
#pragma unroll
    for (int i = 0; i < 4; i++)
#pragma unroll
        for (int j = 0; j < 3; j++)
#pragma unroll
            for (int q = 0; q < 4; q++) acc[i][j][q] = 0.f;

    // ---- stage loader ----
    auto load_stage = [&](int kt) {
        const uint32_t st = sb + (kt % 3) * ST_BYTES;
        const size_t kb = (size_t)kt * BKB;
#pragma unroll
        for (int i = 0; i < 2; i++) {
            const int row = lrow + i * 64;
            const uint32_t sw = (lch ^ ((row >> 1) & 3)) * 16;
            const size_t go = (size_t)row * rs + kb + lch * 16;
            cp16(st + ST_AHI + row * 64 + sw, A0 + go);
            cp16(st + ST_ALO + row * 64 + sw, A1 + go);
        }
        {
            const int row = lrow;        // B rows 0..63
            const uint32_t sw = (lch ^ ((row >> 1) & 3)) * 16;
            const size_t go = (size_t)row * rs + kb + lch * 16;
            cp16(st + ST_BHI + row * 64 + sw, B0 + go);
            cp16(st + ST_BLO + row * 64 + sw, B1 + go);
        }
        if (lrow < 32) {                 // B rows 64..95
            const int row = lrow + 64;
            const uint32_t sw = (lch ^ ((row >> 1) & 3)) * 16;
            const size_t go = (size_t)row * rs + kb + lch * 16;
            cp16(st + ST_BHI + row * 64 + sw, B0 + go);
            cp16(st + ST_BLO + row * 64 + sw, B1 + go);
        }
    };

    // prologue: stages 0..1
    load_stage(0);
    asm volatile("cp.async.commit_group;" ::: "memory");
    load_stage(1);
    asm volatile("cp.async.commit_group;" ::: "memory");

    for (int kt = 0; kt < nk; kt++) {
        asm volatile("cp.async.wait_group 1;" ::: "memory");
        __syncthreads();
        if (kt + 2 < nk) load_stage(kt + 2);
        asm volatile("cp.async.commit_group;" ::: "memory");

        const uint32_t st = sb + (kt % 3) * ST_BYTES;
#pragma unroll
        for (int ks = 0; ks < 2; ks++) {
            uint32_t ah[4][4], al[4][4];
#pragma unroll
            for (int mt = 0; mt < 4; mt++) {
                const int arow = mbase + mt * 16 + (lane & 15);
                const int ac = (ks * 2 + (lane >> 4)) ^ ((arow >> 1) & 3);
                const uint32_t off = arow * 64 + ac * 16;
                LDSM4(ah[mt][0], ah[mt][1], ah[mt][2], ah[mt][3],
                      st + ST_AHI + off);
                LDSM4(al[mt][0], al[mt][1], al[mt][2], al[mt][3],
                      st + ST_ALO + off);
            }
            uint32_t bh[3][2], bl[3][2];
            {   // tiles 0,1 (rows nbase..nbase+15) via x4
                const int brow = nbase + ((lane >> 4) & 1) * 8 + (lane & 7);
                const int bc = (ks * 2 + ((lane >> 3) & 1)) ^ ((brow >> 1) & 3);
                const uint32_t off = brow * 64 + bc * 16;
                LDSM4(bh[0][0], bh[0][1], bh[1][0], bh[1][1], st + ST_BHI + off);
                LDSM4(bl[0][0], bl[0][1], bl[1][0], bl[1][1], st + ST_BLO + off);
            }
            {   // tile 2 (rows nbase+16..nbase+23) via x2
                const int brow = nbase + 16 + (lane & 7);
                const int bc = (ks * 2 + ((lane >> 3) & 1)) ^ ((brow >> 1) & 3);
                const uint32_t off = brow * 64 + bc * 16;
                LDSM2(bh[2][0], bh[2][1], st + ST_BHI + off);
                LDSM2(bl[2][0], bl[2][1], st + ST_BLO + off);
            }
#pragma unroll
            for (int mt = 0; mt < 4; mt++)
#pragma unroll
                for (int nt = 0; nt < 3; nt++) {
                    MMA16816(acc[mt][nt], ah[mt][0], ah[mt][1], ah[mt][2],
                             ah[mt][3], bh[nt][0], bh[nt][1]);
                    MMA16816(acc[mt][nt], ah[mt][0], ah[mt][1], ah[mt][2],
                             ah[mt][3], bl[nt][0], bl[nt][1]);
                    MMA16816(acc[mt][nt], al[mt][0], al[mt][1], al[mt][2],
                             al[mt][3], bh[nt][0], bh[nt][1]);
                }
        }
    }

    // ---- epilogue ----
    __syncthreads();
#pragma unroll
    for (int mt = 0; mt < 4; mt++) {
        const int r0 = bm + mbase + mt * 16 + (lane >> 2);
#pragma unroll
        for (int nt = 0; nt < 3; nt++) {
            const int col = bn + nbase + nt * 8 + (lane & 3) * 2;
            const float b0 = __ldg(&bias[col]);
            const float b1 = __ldg(&bias[col + 1]);
            float2 v0, v1;
            v0.x = acc[mt][nt][0] + b0;
            v0.y = acc[mt][nt][1] + b1;
            v1.x = acc[mt][nt][2] + b0;
            v1.y = acc[mt][nt][3] + b1;
            if (SP) {
                v0.x = softplusf(v0.x); v0.y = softplusf(v0.y);
                v1.x = softplusf(v1.x); v1.y = softplusf(v1.y);
            }
            *(float2*)&C[(size_t)r0 * Nn + col]       = v0;
            *(float2*)&C[(size_t)(r0 + 8) * Nn + col] = v1;
        }
    }
}

// ---------------------------------------------------------------------------
// fp32 -> bf16 hi/lo split
// ---------------------------------------------------------------------------
__global__ void __launch_bounds__(256)
split_kernel(const float* __restrict__ in, __nv_bfloat16* __restrict__ hi,
             __nv_bfloat16* __restrict__ lo, int n)
{
    int i = blockIdx.x * 256 + threadIdx.x;
    if (i < n) {
        float v = in[i];
        __nv_bfloat16 h = __float2bfloat16(v);
        hi[i] = h;
        lo[i] = __float2bfloat16(v - __bfloat162float(h));
    }
}

// ---------------------------------------------------------------------------
// Bt / Ct: per-row GEMV onto 16+16 outputs. One block per row.
// ---------------------------------------------------------------------------
__global__ void __launch_bounds__(256)
bc_kernel(const float* __restrict__ x, const float* __restrict__ WB,
          const float* __restrict__ WC, float* __restrict__ Bt,
          float* __restrict__ Ct)
{
    __shared__ float xs[DMODEL];
    const int row = blockIdx.x;
    const int t = threadIdx.x;
    for (int i = t; i < DMODEL; i += 256)
        xs[i] = x[(size_t)row * DMODEL + i];
    __syncthreads();

    const int warp = t >> 5;
    const int lane = t & 31;
#pragma unroll
    for (int o = 0; o < 4; o++) {
        const int j = warp * 4 + o;
        const float* W = (j < DSTATE) ? (WB + (size_t)j * DMODEL)
                                      : (WC + (size_t)(j - DSTATE) * DMODEL);
        float s = 0.f;
#pragma unroll 4
        for (int k = lane; k < DMODEL; k += 32)
            s = fmaf(xs[k], W[k], s);
#pragma unroll
        for (int off = 16; off; off >>= 1)
            s += __shfl_xor_sync(0xffffffffu, s, off);
        if (lane == 0) {
            if (j < DSTATE) Bt[(size_t)row * DSTATE + j] = s;
            else            Ct[(size_t)row * DSTATE + (j - DSTATE)] = s;
        }
    }
}

// ---------------------------------------------------------------------------
// Selective scan: one thread per (b,d,n) chain; emits flat as bf16 hi/lo.
// ---------------------------------------------------------------------------
__global__ void __launch_bounds__(128)
scan_kernel(const float* __restrict__ delta, const float* __restrict__ Btg,
            const float* __restrict__ Ctg, const float* __restrict__ loglam,
            __nv_bfloat16* __restrict__ yhi, __nv_bfloat16* __restrict__ ylo)
{
    const int tid = blockIdx.x * 128 + threadIdx.x;
    const int b = tid / (DMODEL * DSTATE);
    const int r = tid % (DMODEL * DSTATE);
    const int d = r / DSTATE;
    const int n = r % DSTATE;

    const float lam = softplusf(loglam[d * DSTATE + n]);

    const float* dp = delta + (size_t)b * SEQLEN * DMODEL + d;
    const float* bp = Btg + (size_t)b * SEQLEN * DSTATE + n;
    const float* cp = Ctg + (size_t)b * SEQLEN * DSTATE + n;
    __nv_bfloat16* hp = yhi + (size_t)b * SEQLEN * KFLAT + r;
    __nv_bfloat16* lp = ylo + (size_t)b * SEQLEN * KFLAT + r;

    float h = 0.f;
    for (int l = 0; l < SEQLEN; l++) {
        const float dl = __ldg(dp); dp += DMODEL;
        const float bt = __ldg(bp); bp += DSTATE;
        const float ct = __ldg(cp); cp += DSTATE;
        const float a = __expf(-dl * lam);
        h = fmaf(a, h, dl * bt);
        const float y = h * ct;
        const __nv_bfloat16 hv = __float2bfloat16(y);
        *hp = hv;
        *lp = __float2bfloat16(y - __bfloat162float(hv));
        hp += KFLAT;
        lp += KFLAT;
    }
}

// ---------------------------------------------------------------------------
extern "C" void kernel_launch(void* const* d_in, const int* in_sizes, int n_in,
                              void* d_out, int out_size)
{
    const float* x      = (const float*)d_in[0];
    const float* loglam = (const float*)d_in[1];
    const float* Wd     = (const float*)d_in[2];
    const float* bd     = (const float*)d_in[3];
    const float* WB     = (const float*)d_in[4];
    const float* WC     = (const float*)d_in[5];
    const float* Wout   = (const float*)d_in[6];
    const float* bout   = (const float*)d_in[7];
    float* out          = (float*)d_out;

    float *p_delta, *p_Bt, *p_Ct;
    __nv_bfloat16 *p_xhi, *p_xlo, *p_Wdhi, *p_Wdlo, *p_Wouthi, *p_Woutlo,
                  *p_flathi, *p_flatlo;
    cudaGetSymbolAddress((void**)&p_delta,  g_delta);
    cudaGetSymbolAddress((void**)&p_Bt,     g_Bt);
    cudaGetSymbolAddress((void**)&p_Ct,     g_Ct);
    cudaGetSymbolAddress((void**)&p_xhi,    g_xhi);
    cudaGetSymbolAddress((void**)&p_xlo,    g_xlo);
    cudaGetSymbolAddress((void**)&p_Wdhi,   g_Wdhi);
    cudaGetSymbolAddress((void**)&p_Wdlo,   g_Wdlo);
    cudaGetSymbolAddress((void**)&p_Wouthi, g_Wouthi);
    cudaGetSymbolAddress((void**)&p_Woutlo, g_Woutlo);
    cudaGetSymbolAddress((void**)&p_flathi, g_flathi);
    cudaGetSymbolAddress((void**)&p_flatlo, g_flatlo);

    cudaFuncSetAttribute(tgemm<true>,  cudaFuncAttributeMaxDynamicSharedMemorySize, TG_SMEM);
    cudaFuncSetAttribute(tgemm<false>, cudaFuncAttributeMaxDynamicSharedMemorySize, TG_SMEM);

    // splits
    {
        int n1 = MROWS * DMODEL;
        split_kernel<<<(n1 + 255) / 256, 256>>>(x, p_xhi, p_xlo, n1);
        int n2 = DMODEL * DMODEL;
        split_kernel<<<(n2 + 255) / 256, 256>>>(Wd, p_Wdhi, p_Wdlo, n2);
        int n3 = DMODEL * KFLAT;
        split_kernel<<<(n3 + 255) / 256, 256>>>(Wout, p_Wouthi, p_Woutlo, n3);
    }

    // 1. delta = softplus(x @ Wd^T + bd)   [4096 x 768]
    tgemm<true><<<dim3(DMODEL / 96, MROWS / 128), 256, TG_SMEM>>>(
        p_xhi, p_xlo, p_Wdhi, p_Wdlo, bd, p_delta, DMODEL, DMODEL);

    // 2. Bt, Ct
    bc_kernel<<<MROWS, 256>>>(x, WB, WC, p_Bt, p_Ct);

    // 3. scan -> flat hi/lo [4096 x 12288]
    scan_kernel<<<(BATCH * DMODEL * DSTATE) / 128, 128>>>(
        p_delta, p_Bt, p_Ct, loglam, p_flathi, p_flatlo);

    // 4. out = flat @ Wout^T + bout   [4096 x 768]
    tgemm<false><<<dim3(DMODEL / 96, MROWS / 128), 256, TG_SMEM>>>(
        p_flathi, p_flatlo, p_Wouthi, p_Woutlo, bout, out, DMODEL, KFLAT);
}

// round 9
// speedup vs baseline: 3.7611x; 1.2802x over previous
#include <cuda_runtime.h>
#include <cuda_bf16.h>
#include <math.h>
#include <stdint.h>

#define BATCH  2
#define SEQLEN 2048
#define DMODEL 768
#define DSTATE 16
#define MROWS  (BATCH * SEQLEN)          // 4096
#define KFLAT  (DMODEL * DSTATE)         // 12288
#define NSEG   16
#define TSEG   (SEQLEN / NSEG)           // 128
#define DN     KFLAT                     // 12288 (d,n) pairs

// ---------------- scratch (device globals; no allocation allowed) ----------
__device__ float g_delta[(size_t)MROWS * DMODEL];
__device__ float g_Bt[(size_t)MROWS * DSTATE];
__device__ float g_Ct[(size_t)MROWS * DSTATE];
__device__ float g_hend[(size_t)BATCH * NSEG * DN];
__device__ float g_D[(size_t)BATCH * NSEG * DN];
__device__ float g_hstart[(size_t)BATCH * NSEG * DN];
__device__ __nv_bfloat16 g_xhi[(size_t)MROWS * DMODEL];
__device__ __nv_bfloat16 g_xlo[(size_t)MROWS * DMODEL];
__device__ __nv_bfloat16 g_Wdhi[(size_t)DMODEL * DMODEL];
__device__ __nv_bfloat16 g_Wdlo[(size_t)DMODEL * DMODEL];
__device__ __nv_bfloat16 g_Wouthi[(size_t)DMODEL * KFLAT];
__device__ __nv_bfloat16 g_Woutlo[(size_t)DMODEL * KFLAT];
__device__ __nv_bfloat16 g_flathi[(size_t)MROWS * KFLAT];
__device__ __nv_bfloat16 g_flatlo[(size_t)MROWS * KFLAT];

__device__ __forceinline__ float softplusf(float x) {
    if (x > 20.f) return x;
    return log1pf(__expf(x));
}

__device__ __forceinline__ uint32_t smem_u32(const void* p) {
    uint32_t a;
    asm("{ .reg .u64 t; cvta.to.shared.u64 t, %1; cvt.u32.u64 %0, t; }"
        : "=r"(a) : "l"(p));
    return a;
}

__device__ __forceinline__ void cp16(uint32_t dst, const void* src) {
    asm volatile("cp.async.cg.shared.global [%0], [%1], 16;"
                 :: "r"(dst), "l"(src) : "memory");
}

#define MMA16816(d, a0, a1, a2, a3, b0, b1)                                   \
    asm volatile(                                                             \
        "mma.sync.aligned.m16n8k16.row.col.f32.bf16.bf16.f32 "                \
        "{%0,%1,%2,%3},{%4,%5,%6,%7},{%8,%9},{%0,%1,%2,%3};"                  \
        : "+f"((d)[0]), "+f"((d)[1]), "+f"((d)[2]), "+f"((d)[3])              \
        : "r"(a0), "r"(a1), "r"(a2), "r"(a3), "r"(b0), "r"(b1))

#define LDSM4(r0, r1, r2, r3, addr)                                           \
    asm volatile("ldmatrix.sync.aligned.m8n8.x4.shared.b16 {%0,%1,%2,%3}, [%4];" \
                 : "=r"(r0), "=r"(r1), "=r"(r2), "=r"(r3) : "r"(addr))

#define LDSM2(r0, r1, addr)                                                   \
    asm volatile("ldmatrix.sync.aligned.m8n8.x2.shared.b16 {%0,%1}, [%2];"    \
                 : "=r"(r0), "=r"(r1) : "r"(addr))

// ---------------------------------------------------------------------------
// Tensor-core NT GEMM (unchanged from R8): BM=128, BN=96, BK=32, 3-stage,
// warp tile 64x24, 2 CTAs/SM.
// ---------------------------------------------------------------------------
#define BKB       64
#define ST_AHI    0
#define ST_ALO    8192
#define ST_BHI    16384
#define ST_BLO    22528
#define ST_BYTES  28672
#define TG_SMEM   (3 * ST_BYTES)

template <bool SP>
__global__ void __launch_bounds__(256, 2)
tgemm(const __nv_bfloat16* __restrict__ Ahi, const __nv_bfloat16* __restrict__ Alo,
      const __nv_bfloat16* __restrict__ Bhi, const __nv_bfloat16* __restrict__ Blo,
      const float* __restrict__ bias, float* __restrict__ C, int Nn, int K)
{
    extern __shared__ char dsm[];
    const uint32_t sb = smem_u32(dsm);
    const int t = threadIdx.x, wid = t >> 5, lane = t & 31;
    const int bm = blockIdx.y * 128, bn = blockIdx.x * 96;

    const size_t rs = (size_t)K * 2;
    const char* A0 = (const char*)Ahi + (size_t)bm * rs;
    const char* A1 = (const char*)Alo + (size_t)bm * rs;
    const char* B0 = (const char*)Bhi + (size_t)bn * rs;
    const char* B1 = (const char*)Blo + (size_t)bn * rs;

    const int nk = K / 32;

    const int lch  = t & 3;
    const int lrow = t >> 2;

    const int wm = wid >> 2, wn = wid & 3;
    const int mbase = wm * 64, nbase = wn * 24;

    float acc[4][3][4];
#pragma unroll
    for (int i = 0; i < 4; i++)
#pragma unroll
        for (int j = 0; j < 3; j++)
#pragma unroll
            for (int q = 0; q < 4; q++) acc[i][j][q] = 0.f;

    auto load_stage = [&](int kt) {
        const uint32_t st = sb + (kt % 3) * ST_BYTES;
        const size_t kb = (size_t)kt * BKB;
#pragma unroll
        for (int i = 0; i < 2; i++) {
            const int row = lrow + i * 64;
            const uint32_t sw = (lch ^ ((row >> 1) & 3)) * 16;
            const size_t go = (size_t)row * rs + kb + lch * 16;
            cp16(st + ST_AHI + row * 64 + sw, A0 + go);
            cp16(st + ST_ALO + row * 64 + sw, A1 + go);
        }
        {
            const int row = lrow;
            const uint32_t sw = (lch ^ ((row >> 1) & 3)) * 16;
            const size_t go = (size_t)row * rs + kb + lch * 16;
            cp16(st + ST_BHI + row * 64 + sw, B0 + go);
            cp16(st + ST_BLO + row * 64 + sw, B1 + go);
        }
        if (lrow < 32) {
            const int row = lrow + 64;
            const uint32_t sw = (lch ^ ((row >> 1) & 3)) * 16;
            const size_t go = (size_t)row * rs + kb + lch * 16;
            cp16(st + ST_BHI + row * 64 + sw, B0 + go);
            cp16(st + ST_BLO + row * 64 + sw, B1 + go);
        }
    };

    load_stage(0);
    asm volatile("cp.async.commit_group;" ::: "memory");
    load_stage(1);
    asm volatile("cp.async.commit_group;" ::: "memory");

    for (int kt = 0; kt < nk; kt++) {
        asm volatile("cp.async.wait_group 1;" ::: "memory");
        __syncthreads();
        if (kt + 2 < nk) load_stage(kt + 2);
        asm volatile("cp.async.commit_group;" ::: "memory");

        const uint32_t st = sb + (kt % 3) * ST_BYTES;
#pragma unroll
        for (int ks = 0; ks < 2; ks++) {
            uint32_t ah[4][4], al[4][4];
#pragma unroll
            for (int mt = 0; mt < 4; mt++) {
                const int arow = mbase + mt * 16 + (lane & 15);
                const int ac = (ks * 2 + (lane >> 4)) ^ ((arow >> 1) & 3);
                const uint32_t off = arow * 64 + ac * 16;
                LDSM4(ah[mt][0], ah[mt][1], ah[mt][2], ah[mt][3],
                      st + ST_AHI + off);
                LDSM4(al[mt][0], al[mt][1], al[mt][2], al[mt][3],
                      st + ST_ALO + off);
            }
            uint32_t bh[3][2], bl[3][2];
            {
                const int brow = nbase + ((lane >> 4) & 1) * 8 + (lane & 7);
                const int bc = (ks * 2 + ((lane >> 3) & 1)) ^ ((brow >> 1) & 3);
                const uint32_t off = brow * 64 + bc * 16;
                LDSM4(bh[0][0], bh[0][1], bh[1][0], bh[1][1], st + ST_BHI + off);
                LDSM4(bl[0][0], bl[0][1], bl[1][0], bl[1][1], st + ST_BLO + off);
            }
            {
                const int brow = nbase + 16 + (lane & 7);
                const int bc = (ks * 2 + ((lane >> 3) & 1)) ^ ((brow >> 1) & 3);
                const uint32_t off = brow * 64 + bc * 16;
                LDSM2(bh[2][0], bh[2][1], st + ST_BHI + off);
                LDSM2(bl[2][0], bl[2][1], st + ST_BLO + off);
            }
#pragma unroll
            for (int mt = 0; mt < 4; mt++)
#pragma unroll
                for (int nt = 0; nt < 3; nt++) {
                    MMA16816(acc[mt][nt], ah[mt][0], ah[mt][1], ah[mt][2],
                             ah[mt][3], bh[nt][0], bh[nt][1]);
                    MMA16816(acc[mt][nt], ah[mt][0], ah[mt][1], ah[mt][2],
                             ah[mt][3], bl[nt][0], bl[nt][1]);
                    MMA16816(acc[mt][nt], al[mt][0], al[mt][1], al[mt][2],
                             al[mt][3], bh[nt][0], bh[nt][1]);
                }
        }
    }

    __syncthreads();
#pragma unroll
    for (int mt = 0; mt < 4; mt++) {
        const int r0 = bm + mbase + mt * 16 + (lane >> 2);
#pragma unroll
        for (int nt = 0; nt < 3; nt++) {
            const int col = bn + nbase + nt * 8 + (lane & 3) * 2;
            const float b0 = __ldg(&bias[col]);
            const float b1 = __ldg(&bias[col + 1]);
            float2 v0, v1;
            v0.x = acc[mt][nt][0] + b0;
            v0.y = acc[mt][nt][1] + b1;
            v1.x = acc[mt][nt][2] + b0;
            v1.y = acc[mt][nt][3] + b1;
            if (SP) {
                v0.x = softplusf(v0.x); v0.y = softplusf(v0.y);
                v1.x = softplusf(v1.x); v1.y = softplusf(v1.y);
            }
            *(float2*)&C[(size_t)r0 * Nn + col]       = v0;
            *(float2*)&C[(size_t)(r0 + 8) * Nn + col] = v1;
        }
    }
}

// ---------------------------------------------------------------------------
// fp32 -> bf16 hi/lo split
// ---------------------------------------------------------------------------
__global__ void __launch_bounds__(256)
split_kernel(const float* __restrict__ in, __nv_bfloat16* __restrict__ hi,
             __nv_bfloat16* __restrict__ lo, int n)
{
    int i = blockIdx.x * 256 + threadIdx.x;
    if (i < n) {
        float v = in[i];
        __nv_bfloat16 h = __float2bfloat16(v);
        hi[i] = h;
        lo[i] = __float2bfloat16(v - __bfloat162float(h));
    }
}

// ---------------------------------------------------------------------------
// Bt / Ct: per-row GEMV onto 16+16 outputs. One block per row.
// ---------------------------------------------------------------------------
__global__ void __launch_bounds__(256)
bc_kernel(const float* __restrict__ x, const float* __restrict__ WB,
          const float* __restrict__ WC, float* __restrict__ Bt,
          float* __restrict__ Ct)
{
    __shared__ float xs[DMODEL];
    const int row = blockIdx.x;
    const int t = threadIdx.x;
    for (int i = t; i < DMODEL; i += 256)
        xs[i] = x[(size_t)row * DMODEL + i];
    __syncthreads();

    const int warp = t >> 5;
    const int lane = t & 31;
#pragma unroll
    for (int o = 0; o < 4; o++) {
        const int j = warp * 4 + o;
        const float* W = (j < DSTATE) ? (WB + (size_t)j * DMODEL)
                                      : (WC + (size_t)(j - DSTATE) * DMODEL);
        float s = 0.f;
#pragma unroll 4
        for (int k = lane; k < DMODEL; k += 32)
            s = fmaf(xs[k], W[k], s);
#pragma unroll
        for (int off = 16; off; off >>= 1)
            s += __shfl_xor_sync(0xffffffffu, s, off);
        if (lane == 0) {
            if (j < DSTATE) Bt[(size_t)row * DSTATE + j] = s;
            else            Ct[(size_t)row * DSTATE + (j - DSTATE)] = s;
        }
    }
}

// ---------------------------------------------------------------------------
// Segmented scan, phase A: per (b,seg,d,n), run TSEG steps from h=0,
// emit segment carry h_end0 and total decay D = exp(-lam * sum(delta)).
// ---------------------------------------------------------------------------
__global__ void __launch_bounds__(256)
scan_a(const float* __restrict__ delta, const float* __restrict__ Btg,
       const float* __restrict__ loglam, float* __restrict__ hend,
       float* __restrict__ Dg)
{
    const int tid = blockIdx.x * 256 + threadIdx.x;   // < BATCH*NSEG*DN
    const int b   = tid / (NSEG * DN);
    const int rem = tid % (NSEG * DN);
    const int seg = rem / DN;
    const int r   = rem % DN;
    const int d   = r / DSTATE;
    const int n   = r % DSTATE;

    const float lam = softplusf(loglam[r]);
    const int l0 = seg * TSEG;

    const float* dp = delta + ((size_t)b * SEQLEN + l0) * DMODEL + d;
    const float* bp = Btg + ((size_t)b * SEQLEN + l0) * DSTATE + n;

    float h = 0.f, sd = 0.f;
#pragma unroll 4
    for (int l = 0; l < TSEG; l++) {
        const float dl = __ldg(dp); dp += DMODEL;
        const float bt = __ldg(bp); bp += DSTATE;
        const float a = __expf(-dl * lam);
        h = fmaf(a, h, dl * bt);
        sd += dl;
    }
    hend[tid] = h;
    Dg[tid] = __expf(-sd * lam);
}

// ---------------------------------------------------------------------------
// Segmented scan, phase B: propagate carries across NSEG segments.
// ---------------------------------------------------------------------------
__global__ void __launch_bounds__(256)
scan_b(const float* __restrict__ hend, const float* __restrict__ Dg,
       float* __restrict__ hstart)
{
    const int tid = blockIdx.x * 256 + threadIdx.x;   // < BATCH*DN
    const int b = tid / DN;
    const int r = tid % DN;

    float h = 0.f;
#pragma unroll
    for (int s = 0; s < NSEG; s++) {
        const size_t idx = ((size_t)b * NSEG + s) * DN + r;
        hstart[idx] = h;
        h = fmaf(Dg[idx], h, hend[idx]);
    }
}

// ---------------------------------------------------------------------------
// Segmented scan, phase C: re-run segments from correct h_start, write y
// split into bf16 hi/lo.
// ---------------------------------------------------------------------------
__global__ void __launch_bounds__(256)
scan_c(const float* __restrict__ delta, const float* __restrict__ Btg,
       const float* __restrict__ Ctg, const float* __restrict__ loglam,
       const float* __restrict__ hstart,
       __nv_bfloat16* __restrict__ yhi, __nv_bfloat16* __restrict__ ylo)
{
    const int tid = blockIdx.x * 256 + threadIdx.x;   // < BATCH*NSEG*DN
    const int b   = tid / (NSEG * DN);
    const int rem = tid % (NSEG * DN);
    const int seg = rem / DN;
    const int r   = rem % DN;
    const int d   = r / DSTATE;
    const int n   = r % DSTATE;

    const float lam = softplusf(loglam[r]);
    const int l0 = seg * TSEG;

    const float* dp = delta + ((size_t)b * SEQLEN + l0) * DMODEL + d;
    const float* bp = Btg + ((size_t)b * SEQLEN + l0) * DSTATE + n;
    const float* cp = Ctg + ((size_t)b * SEQLEN + l0) * DSTATE + n;
    __nv_bfloat16* hp = yhi + ((size_t)b * SEQLEN + l0) * KFLAT + r;
    __nv_bfloat16* lp = ylo + ((size_t)b * SEQLEN + l0) * KFLAT + r;

    float h = hstart[tid];
#pragma unroll 4
    for (int l = 0; l < TSEG; l++) {
        const float dl = __ldg(dp); dp += DMODEL;
        const float bt = __ldg(bp); bp += DSTATE;
        const float ct = __ldg(cp); cp += DSTATE;
        const float a = __expf(-dl * lam);
        h = fmaf(a, h, dl * bt);
        const float y = h * ct;
        const __nv_bfloat16 hv = __float2bfloat16(y);
        *hp = hv;
        *lp = __float2bfloat16(y - __bfloat162float(hv));
        hp += KFLAT;
        lp += KFLAT;
    }
}

// ---------------------------------------------------------------------------
extern "C" void kernel_launch(void* const* d_in, const int* in_sizes, int n_in,
                              void* d_out, int out_size)
{
    const float* x      = (const float*)d_in[0];
    const float* loglam = (const float*)d_in[1];
    const float* Wd     = (const float*)d_in[2];
    const float* bd     = (const float*)d_in[3];
    const float* WB     = (const float*)d_in[4];
    const float* WC     = (const float*)d_in[5];
    const float* Wout   = (const float*)d_in[6];
    const float* bout   = (const float*)d_in[7];
    float* out          = (float*)d_out;

    float *p_delta, *p_Bt, *p_Ct, *p_hend, *p_D, *p_hstart;
    __nv_bfloat16 *p_xhi, *p_xlo, *p_Wdhi, *p_Wdlo, *p_Wouthi, *p_Woutlo,
                  *p_flathi, *p_flatlo;
    cudaGetSymbolAddress((void**)&p_delta,  g_delta);
    cudaGetSymbolAddress((void**)&p_Bt,     g_Bt);
    cudaGetSymbolAddress((void**)&p_Ct,     g_Ct);
    cudaGetSymbolAddress((void**)&p_hend,   g_hend);
    cudaGetSymbolAddress((void**)&p_D,      g_D);
    cudaGetSymbolAddress((void**)&p_hstart, g_hstart);
    cudaGetSymbolAddress((void**)&p_xhi,    g_xhi);
    cudaGetSymbolAddress((void**)&p_xlo,    g_xlo);
    cudaGetSymbolAddress((void**)&p_Wdhi,   g_Wdhi);
    cudaGetSymbolAddress((void**)&p_Wdlo,   g_Wdlo);
    cudaGetSymbolAddress((void**)&p_Wouthi, g_Wouthi);
    cudaGetSymbolAddress((void**)&p_Woutlo, g_Woutlo);
    cudaGetSymbolAddress((void**)&p_flathi, g_flathi);
    cudaGetSymbolAddress((void**)&p_flatlo, g_flatlo);

    cudaFuncSetAttribute(tgemm<true>,  cudaFuncAttributeMaxDynamicSharedMemorySize, TG_SMEM);
    cudaFuncSetAttribute(tgemm<false>, cudaFuncAttributeMaxDynamicSharedMemorySize, TG_SMEM);

    // splits
    {
        int n1 = MROWS * DMODEL;
        split_kernel<<<(n1 + 255) / 256, 256>>>(x, p_xhi, p_xlo, n1);
        int n2 = DMODEL * DMODEL;
        split_kernel<<<(n2 + 255) / 256, 256>>>(Wd, p_Wdhi, p_Wdlo, n2);
        int n3 = DMODEL * KFLAT;
        split_kernel<<<(n3 + 255) / 256, 256>>>(Wout, p_Wouthi, p_Woutlo, n3);
    }

    // 1. delta = softplus(x @ Wd^T + bd)   [4096 x 768]
    tgemm<true><<<dim3(DMODEL / 96, MROWS / 128), 256, TG_SMEM>>>(
        p_xhi, p_xlo, p_Wdhi, p_Wdlo, bd, p_delta, DMODEL, DMODEL);

    // 2. Bt, Ct
    bc_kernel<<<MROWS, 256>>>(x, WB, WC, p_Bt, p_Ct);

    // 3. segmented scan -> flat hi/lo [4096 x 12288]
    scan_a<<<(BATCH * NSEG * DN) / 256, 256>>>(p_delta, p_Bt, loglam, p_hend, p_D);
    scan_b<<<(BATCH * DN) / 256, 256>>>(p_hend, p_D, p_hstart);
    scan_c<<<(BATCH * NSEG * DN) / 256, 256>>>(p_delta, p_Bt, p_Ct, loglam,
                                               p_hstart, p_flathi, p_flatlo);

    // 4. out = flat @ Wout^T + bout   [4096 x 768]
    tgemm<false><<<dim3(DMODEL / 96, MROWS / 128), 256, TG_SMEM>>>(
        p_flathi, p_flatlo, p_Wouthi, p_Woutlo, bout, out, DMODEL, KFLAT);
}

// round 10
// speedup vs baseline: 4.9029x; 1.3036x over previous
#include <cuda_runtime.h>
#include <cuda_bf16.h>
#include <cuda_fp16.h>
#include <math.h>
#include <stdint.h>

#define BATCH  2
#define SEQLEN 2048
#define DMODEL 768
#define DSTATE 16
#define MROWS  (BATCH * SEQLEN)          // 4096
#define KFLAT  (DMODEL * DSTATE)         // 12288
#define NSEG   16
#define TSEG   (SEQLEN / NSEG)           // 128
#define DN     KFLAT                     // 12288 (d,n) pairs

// ---------------- scratch (device globals; no allocation allowed) ----------
__device__ float g_delta[(size_t)MROWS * DMODEL];
__device__ float g_Bt[(size_t)MROWS * DSTATE];
__device__ float g_Ct[(size_t)MROWS * DSTATE];
__device__ float g_hend[(size_t)BATCH * NSEG * DN];
__device__ float g_D[(size_t)BATCH * NSEG * DN];
__device__ float g_hstart[(size_t)BATCH * NSEG * DN];
__device__ __nv_bfloat16 g_xhi[(size_t)MROWS * DMODEL];
__device__ __nv_bfloat16 g_xlo[(size_t)MROWS * DMODEL];
__device__ __nv_bfloat16 g_Wdhi[(size_t)DMODEL * DMODEL];
__device__ __nv_bfloat16 g_Wdlo[(size_t)DMODEL * DMODEL];
__device__ __half g_Wouthi[(size_t)DMODEL * KFLAT];
__device__ __half g_Woutlo[(size_t)DMODEL * KFLAT];
__device__ __half g_flat[(size_t)MROWS * KFLAT];          // single fp16 y

__device__ __forceinline__ float softplusf(float x) {
    if (x > 20.f) return x;
    return log1pf(__expf(x));
}

__device__ __forceinline__ uint32_t smem_u32(const void* p) {
    uint32_t a;
    asm("{ .reg .u64 t; cvta.to.shared.u64 t, %1; cvt.u32.u64 %0, t; }"
        : "=r"(a) : "l"(p));
    return a;
}

__device__ __forceinline__ void cp16(uint32_t dst, const void* src) {
    asm volatile("cp.async.cg.shared.global [%0], [%1], 16;"
                 :: "r"(dst), "l"(src) : "memory");
}

#define MMA16816BF(d, a0, a1, a2, a3, b0, b1)                                 \
    asm volatile(                                                             \
        "mma.sync.aligned.m16n8k16.row.col.f32.bf16.bf16.f32 "                \
        "{%0,%1,%2,%3},{%4,%5,%6,%7},{%8,%9},{%0,%1,%2,%3};"                  \
        : "+f"((d)[0]), "+f"((d)[1]), "+f"((d)[2]), "+f"((d)[3])              \
        : "r"(a0), "r"(a1), "r"(a2), "r"(a3), "r"(b0), "r"(b1))

#define MMA16816FP(d, a0, a1, a2, a3, b0, b1)                                 \
    asm volatile(                                                             \
        "mma.sync.aligned.m16n8k16.row.col.f32.f16.f16.f32 "                  \
        "{%0,%1,%2,%3},{%4,%5,%6,%7},{%8,%9},{%0,%1,%2,%3};"                  \
        : "+f"((d)[0]), "+f"((d)[1]), "+f"((d)[2]), "+f"((d)[3])              \
        : "r"(a0), "r"(a1), "r"(a2), "r"(a3), "r"(b0), "r"(b1))

#define LDSM4(r0, r1, r2, r3, addr)                                           \
    asm volatile("ldmatrix.sync.aligned.m8n8.x4.shared.b16 {%0,%1,%2,%3}, [%4];" \
                 : "=r"(r0), "=r"(r1), "=r"(r2), "=r"(r3) : "r"(addr))

#define LDSM2(r0, r1, addr)                                                   \
    asm volatile("ldmatrix.sync.aligned.m8n8.x2.shared.b16 {%0,%1}, [%2];"    \
                 : "=r"(r0), "=r"(r1) : "r"(addr))

// ---------------------------------------------------------------------------
// bf16 3-term GEMM (delta path; unchanged from R8): BM=128, BN=96, BK=32,
// 3-stage, warp tile 64x24, 2 CTAs/SM.
// ---------------------------------------------------------------------------
#define BKB       64
#define ST_AHI    0
#define ST_ALO    8192
#define ST_BHI    16384
#define ST_BLO    22528
#define ST_BYTES  28672
#define TG_SMEM   (3 * ST_BYTES)

template <bool SP>
__global__ void __launch_bounds__(256, 2)
tgemm(const __nv_bfloat16* __restrict__ Ahi, const __nv_bfloat16* __restrict__ Alo,
      const __nv_bfloat16* __restrict__ Bhi, const __nv_bfloat16* __restrict__ Blo,
      const float* __restrict__ bias, float* __restrict__ C, int Nn, int K)
{
    extern __shared__ char dsm[];
    const uint32_t sb = smem_u32(dsm);
    const int t = threadIdx.x, wid = t >> 5, lane = t & 31;
    const int bm = blockIdx.y * 128, bn = blockIdx.x * 96;

    const size_t rs = (size_t)K * 2;
    const char* A0 = (const char*)Ahi + (size_t)bm * rs;
    const char* A1 = (const char*)Alo + (size_t)bm * rs;
    const char* B0 = (const char*)Bhi + (size_t)bn * rs;
    const char* B1 = (const char*)Blo + (size_t)bn * rs;

    const int nk = K / 32;
    const int lch  = t & 3;
    const int lrow = t >> 2;
    const int wm = wid >> 2, wn = wid & 3;
    const int mbase = wm * 64, nbase = wn * 24;

    float acc[4][3][4];
#pragma unroll
    for (int i = 0; i < 4; i++)
#pragma unroll
        for (int j = 0; j < 3; j++)
#pragma unroll
            for (int q = 0; q < 4; q++) acc[i][j][q] = 0.f;

    auto load_stage = [&](int kt) {
        const uint32_t st = sb + (kt % 3) * ST_BYTES;
        const size_t kb = (size_t)kt * BKB;
#pragma unroll
        for (int i = 0; i < 2; i++) {
            const int row = lrow + i * 64;
            const uint32_t sw = (lch ^ ((row >> 1) & 3)) * 16;
            const size_t go = (size_t)row * rs + kb + lch * 16;
            cp16(st + ST_AHI + row * 64 + sw, A0 + go);
            cp16(st + ST_ALO + row * 64 + sw, A1 + go);
        }
        {
            const int row = lrow;
            const uint32_t sw = (lch ^ ((row >> 1) & 3)) * 16;
            const size_t go = (size_t)row * rs + kb + lch * 16;
            cp16(st + ST_BHI + row * 64 + sw, B0 + go);
            cp16(st + ST_BLO + row * 64 + sw, B1 + go);
        }
        if (lrow < 32) {
            const int row = lrow + 64;
            const uint32_t sw = (lch ^ ((row >> 1) & 3)) * 16;
            const size_t go = (size_t)row * rs + kb + lch * 16;
            cp16(st + ST_BHI + row * 64 + sw, B0 + go);
            cp16(st + ST_BLO + row * 64 + sw, B1 + go);
        }
    };

    load_stage(0);
    asm volatile("cp.async.commit_group;" ::: "memory");
    load_stage(1);
    asm volatile("cp.async.commit_group;" ::: "memory");

    for (int kt = 0; kt < nk; kt++) {
        asm volatile("cp.async.wait_group 1;" ::: "memory");
        __syncthreads();
        if (kt + 2 < nk) load_stage(kt + 2);
        asm volatile("cp.async.commit_group;" ::: "memory");

        const uint32_t st = sb + (kt % 3) * ST_BYTES;
#pragma unroll
        for (int ks = 0; ks < 2; ks++) {
            uint32_t ah[4][4], al[4][4];
#pragma unroll
            for (int mt = 0; mt < 4; mt++) {
                const int arow = mbase + mt * 16 + (lane & 15);
                const int ac = (ks * 2 + (lane >> 4)) ^ ((arow >> 1) & 3);
                const uint32_t off = arow * 64 + ac * 16;
                LDSM4(ah[mt][0], ah[mt][1], ah[mt][2], ah[mt][3],
                      st + ST_AHI + off);
                LDSM4(al[mt][0], al[mt][1], al[mt][2], al[mt][3],
                      st + ST_ALO + off);
            }
            uint32_t bh[3][2], bl[3][2];
            {
                const int brow = nbase + ((lane >> 4) & 1) * 8 + (lane & 7);
                const int bc = (ks * 2 + ((lane >> 3) & 1)) ^ ((brow >> 1) & 3);
                const uint32_t off = brow * 64 + bc * 16;
                LDSM4(bh[0][0], bh[0][1], bh[1][0], bh[1][1], st + ST_BHI + off);
                LDSM4(bl[0][0], bl[0][1], bl[1][0], bl[1][1], st + ST_BLO + off);
            }
            {
                const int brow = nbase + 16 + (lane & 7);
                const int bc = (ks * 2 + ((lane >> 3) & 1)) ^ ((brow >> 1) & 3);
                const uint32_t off = brow * 64 + bc * 16;
                LDSM2(bh[2][0], bh[2][1], st + ST_BHI + off);
                LDSM2(bl[2][0], bl[2][1], st + ST_BLO + off);
            }
#pragma unroll
            for (int mt = 0; mt < 4; mt++)
#pragma unroll
                for (int nt = 0; nt < 3; nt++) {
                    MMA16816BF(acc[mt][nt], ah[mt][0], ah[mt][1], ah[mt][2],
                               ah[mt][3], bh[nt][0], bh[nt][1]);
                    MMA16816BF(acc[mt][nt], ah[mt][0], ah[mt][1], ah[mt][2],
                               ah[mt][3], bl[nt][0], bl[nt][1]);
                    MMA16816BF(acc[mt][nt], al[mt][0], al[mt][1], al[mt][2],
                               al[mt][3], bh[nt][0], bh[nt][1]);
                }
        }
    }

    __syncthreads();
#pragma unroll
    for (int mt = 0; mt < 4; mt++) {
        const int r0 = bm + mbase + mt * 16 + (lane >> 2);
#pragma unroll
        for (int nt = 0; nt < 3; nt++) {
            const int col = bn + nbase + nt * 8 + (lane & 3) * 2;
            const float b0 = __ldg(&bias[col]);
            const float b1 = __ldg(&bias[col + 1]);
            float2 v0, v1;
            v0.x = acc[mt][nt][0] + b0;
            v0.y = acc[mt][nt][1] + b1;
            v1.x = acc[mt][nt][2] + b0;
            v1.y = acc[mt][nt][3] + b1;
            if (SP) {
                v0.x = softplusf(v0.x); v0.y = softplusf(v0.y);
                v1.x = softplusf(v1.x); v1.y = softplusf(v1.y);
            }
            *(float2*)&C[(size_t)r0 * Nn + col]       = v0;
            *(float2*)&C[(size_t)(r0 + 8) * Nn + col] = v1;
        }
    }
}

// ---------------------------------------------------------------------------
// fp16 2-term GEMM (out path): A single fp16, B = W hi/lo fp16.
// C = A*(Bh+Bl)^T + bias. Same tiling: BM=128, BN=96, BK=32, 3-stage,
// warp 64x24, 2 CTAs/SM. Stage: A 8K | Bh 6K | Bl 6K = 20480 B.
// ---------------------------------------------------------------------------
#define S2_A      0
#define S2_BH     8192
#define S2_BL     14336
#define S2_BYTES  20480
#define TG2_SMEM  (3 * S2_BYTES)

__global__ void __launch_bounds__(256, 2)
tgemm_fp16(const __half* __restrict__ A, const __half* __restrict__ Bh,
           const __half* __restrict__ Bl, const float* __restrict__ bias,
           float* __restrict__ C, int Nn, int K)
{
    extern __shared__ char dsm[];
    const uint32_t sb = smem_u32(dsm);
    const int t = threadIdx.x, wid = t >> 5, lane = t & 31;
    const int bm = blockIdx.y * 128, bn = blockIdx.x * 96;

    const size_t rs = (size_t)K * 2;
    const char* Ag = (const char*)A  + (size_t)bm * rs;
    const char* B0 = (const char*)Bh + (size_t)bn * rs;
    const char* B1 = (const char*)Bl + (size_t)bn * rs;

    const int nk = K / 32;
    const int lch  = t & 3;
    const int lrow = t >> 2;
    const int wm = wid >> 2, wn = wid & 3;
    const int mbase = wm * 64, nbase = wn * 24;

    float acc[4][3][4];
#pragma unroll
    for (int i = 0; i < 4; i++)
#pragma unroll
        for (int j = 0; j < 3; j++)
#pragma unroll
            for (int q = 0; q < 4; q++) acc[i][j][q] = 0.f;

    auto load_stage = [&](int kt) {
        const uint32_t st = sb + (kt % 3) * S2_BYTES;
        const size_t kb = (size_t)kt * BKB;
#pragma unroll
        for (int i = 0; i < 2; i++) {
            const int row = lrow + i * 64;
            const uint32_t sw = (lch ^ ((row >> 1) & 3)) * 16;
            const size_t go = (size_t)row * rs + kb + lch * 16;
            cp16(st + S2_A + row * 64 + sw, Ag + go);
        }
        {
            const int row = lrow;
            const uint32_t sw = (lch ^ ((row >> 1) & 3)) * 16;
            const size_t go = (size_t)row * rs + kb + lch * 16;
            cp16(st + S2_BH + row * 64 + sw, B0 + go);
            cp16(st + S2_BL + row * 64 + sw, B1 + go);
        }
        if (lrow < 32) {
            const int row = lrow + 64;
            const uint32_t sw = (lch ^ ((row >> 1) & 3)) * 16;
            const size_t go = (size_t)row * rs + kb + lch * 16;
            cp16(st + S2_BH + row * 64 + sw, B0 + go);
            cp16(st + S2_BL + row * 64 + sw, B1 + go);
        }
    };

    load_stage(0);
    asm volatile("cp.async.commit_group;" ::: "memory");
    load_stage(1);
    asm volatile("cp.async.commit_group;" ::: "memory");

    for (int kt = 0; kt < nk; kt++) {
        asm volatile("cp.async.wait_group 1;" ::: "memory");
        __syncthreads();
        if (kt + 2 < nk) load_stage(kt + 2);
        asm volatile("cp.async.commit_group;" ::: "memory");

        const uint32_t st = sb + (kt % 3) * S2_BYTES;
#pragma unroll
        for (int ks = 0; ks < 2; ks++) {
            uint32_t a[4][4];
#pragma unroll
            for (int mt = 0; mt < 4; mt++) {
                const int arow = mbase + mt * 16 + (lane & 15);
                const int ac = (ks * 2 + (lane >> 4)) ^ ((arow >> 1) & 3);
                const uint32_t off = arow * 64 + ac * 16;
                LDSM4(a[mt][0], a[mt][1], a[mt][2], a[mt][3], st + S2_A + off);
            }
            uint32_t bh[3][2], bl[3][2];
            {
                const int brow = nbase + ((lane >> 4) & 1) * 8 + (lane & 7);
                const int bc = (ks * 2 + ((lane >> 3) & 1)) ^ ((brow >> 1) & 3);
                const uint32_t off = brow * 64 + bc * 16;
                LDSM4(bh[0][0], bh[0][1], bh[1][0], bh[1][1], st + S2_BH + off);
                LDSM4(bl[0][0], bl[0][1], bl[1][0], bl[1][1], st + S2_BL + off);
            }
            {
                const int brow = nbase + 16 + (lane & 7);
                const int bc = (ks * 2 + ((lane >> 3) & 1)) ^ ((brow >> 1) & 3);
                const uint32_t off = brow * 64 + bc * 16;
                LDSM2(bh[2][0], bh[2][1], st + S2_BH + off);
                LDSM2(bl[2][0], bl[2][1], st + S2_BL + off);
            }
#pragma unroll
            for (int mt = 0; mt < 4; mt++)
#pragma unroll
                for (int nt = 0; nt < 3; nt++) {
                    MMA16816FP(acc[mt][nt], a[mt][0], a[mt][1], a[mt][2],
                               a[mt][3], bh[nt][0], bh[nt][1]);
                    MMA16816FP(acc[mt][nt], a[mt][0], a[mt][1], a[mt][2],
                               a[mt][3], bl[nt][0], bl[nt][1]);
                }
        }
    }

    __syncthreads();
#pragma unroll
    for (int mt = 0; mt < 4; mt++) {
        const int r0 = bm + mbase + mt * 16 + (lane >> 2);
#pragma unroll
        for (int nt = 0; nt < 3; nt++) {
            const int col = bn + nbase + nt * 8 + (lane & 3) * 2;
            const float b0 = __ldg(&bias[col]);
            const float b1 = __ldg(&bias[col + 1]);
            float2 v0, v1;
            v0.x = acc[mt][nt][0] + b0;
            v0.y = acc[mt][nt][1] + b1;
            v1.x = acc[mt][nt][2] + b0;
            v1.y = acc[mt][nt][3] + b1;
            *(float2*)&C[(size_t)r0 * Nn + col]       = v0;
            *(float2*)&C[(size_t)(r0 + 8) * Nn + col] = v1;
        }
    }
}

// ---------------------------------------------------------------------------
// fp32 -> bf16 hi/lo split (delta-path operands)
// ---------------------------------------------------------------------------
__global__ void __launch_bounds__(256)
split_bf16(const float* __restrict__ in, __nv_bfloat16* __restrict__ hi,
           __nv_bfloat16* __restrict__ lo, int n)
{
    int i = blockIdx.x * 256 + threadIdx.x;
    if (i < n) {
        float v = in[i];
        __nv_bfloat16 h = __float2bfloat16(v);
        hi[i] = h;
        lo[i] = __float2bfloat16(v - __bfloat162float(h));
    }
}

// fp32 -> fp16 hi/lo split (Wout)
__global__ void __launch_bounds__(256)
split_fp16(const float* __restrict__ in, __half* __restrict__ hi,
           __half* __restrict__ lo, int n)
{
    int i = blockIdx.x * 256 + threadIdx.x;
    if (i < n) {
        float v = in[i];
        __half h = __float2half_rn(v);
        hi[i] = h;
        lo[i] = __float2half_rn(v - __half2float(h));
    }
}

// ---------------------------------------------------------------------------
// Bt / Ct: per-row GEMV onto 16+16 outputs. One block per row.
// ---------------------------------------------------------------------------
__global__ void __launch_bounds__(256)
bc_kernel(const float* __restrict__ x, const float* __restrict__ WB,
          const float* __restrict__ WC, float* __restrict__ Bt,
          float* __restrict__ Ct)
{
    __shared__ float xs[DMODEL];
    const int row = blockIdx.x;
    const int t = threadIdx.x;
    for (int i = t; i < DMODEL; i += 256)
        xs[i] = x[(size_t)row * DMODEL + i];
    __syncthreads();

    const int warp = t >> 5;
    const int lane = t & 31;
#pragma unroll
    for (int o = 0; o < 4; o++) {
        const int j = warp * 4 + o;
        const float* W = (j < DSTATE) ? (WB + (size_t)j * DMODEL)
                                      : (WC + (size_t)(j - DSTATE) * DMODEL);
        float s = 0.f;
#pragma unroll 4
        for (int k = lane; k < DMODEL; k += 32)
            s = fmaf(xs[k], W[k], s);
#pragma unroll
        for (int off = 16; off; off >>= 1)
            s += __shfl_xor_sync(0xffffffffu, s, off);
        if (lane == 0) {
            if (j < DSTATE) Bt[(size_t)row * DSTATE + j] = s;
            else            Ct[(size_t)row * DSTATE + (j - DSTATE)] = s;
        }
    }
}

// ---------------------------------------------------------------------------
// Segmented scan, phase A: per (b,seg,d,n) carry + decay.
// ---------------------------------------------------------------------------
__global__ void __launch_bounds__(256)
scan_a(const float* __restrict__ delta, const float* __restrict__ Btg,
       const float* __restrict__ loglam, float* __restrict__ hend,
       float* __restrict__ Dg)
{
    const int tid = blockIdx.x * 256 + threadIdx.x;
    const int b   = tid / (NSEG * DN);
    const int rem = tid % (NSEG * DN);
    const int seg = rem / DN;
    const int r   = rem % DN;
    const int d   = r / DSTATE;
    const int n   = r % DSTATE;

    const float lam = softplusf(loglam[r]);
    const int l0 = seg * TSEG;

    const float* dp = delta + ((size_t)b * SEQLEN + l0) * DMODEL + d;
    const float* bp = Btg + ((size_t)b * SEQLEN + l0) * DSTATE + n;

    float h = 0.f, sd = 0.f;
#pragma unroll 4
    for (int l = 0; l < TSEG; l++) {
        const float dl = __ldg(dp); dp += DMODEL;
        const float bt = __ldg(bp); bp += DSTATE;
        const float a = __expf(-dl * lam);
        h = fmaf(a, h, dl * bt);
        sd += dl;
    }
    hend[tid] = h;
    Dg[tid] = __expf(-sd * lam);
}

// Phase B: propagate carries across NSEG segments.
__global__ void __launch_bounds__(256)
scan_b(const float* __restrict__ hend, const float* __restrict__ Dg,
       float* __restrict__ hstart)
{
    const int tid = blockIdx.x * 256 + threadIdx.x;
    const int b = tid / DN;
    const int r = tid % DN;

    float h = 0.f;
#pragma unroll
    for (int s = 0; s < NSEG; s++) {
        const size_t idx = ((size_t)b * NSEG + s) * DN + r;
        hstart[idx] = h;
        h = fmaf(Dg[idx], h, hend[idx]);
    }
}

// Phase C: re-run segments from h_start, write y as single fp16.
__global__ void __launch_bounds__(256)
scan_c(const float* __restrict__ delta, const float* __restrict__ Btg,
       const float* __restrict__ Ctg, const float* __restrict__ loglam,
       const float* __restrict__ hstart, __half* __restrict__ yflat)
{
    const int tid = blockIdx.x * 256 + threadIdx.x;
    const int b   = tid / (NSEG * DN);
    const int rem = tid % (NSEG * DN);
    const int seg = rem / DN;
    const int r   = rem % DN;
    const int d   = r / DSTATE;
    const int n   = r % DSTATE;

    const float lam = softplusf(loglam[r]);
    const int l0 = seg * TSEG;

    const float* dp = delta + ((size_t)b * SEQLEN + l0) * DMODEL + d;
    const float* bp = Btg + ((size_t)b * SEQLEN + l0) * DSTATE + n;
    const float* cp = Ctg + ((size_t)b * SEQLEN + l0) * DSTATE + n;
    __half* yp = yflat + ((size_t)b * SEQLEN + l0) * KFLAT + r;

    float h = hstart[tid];
#pragma unroll 4
    for (int l = 0; l < TSEG; l++) {
        const float dl = __ldg(dp); dp += DMODEL;
        const float bt = __ldg(bp); bp += DSTATE;
        const float ct = __ldg(cp); cp += DSTATE;
        const float a = __expf(-dl * lam);
        h = fmaf(a, h, dl * bt);
        *yp = __float2half_rn(h * ct);
        yp += KFLAT;
    }
}

// ---------------------------------------------------------------------------
extern "C" void kernel_launch(void* const* d_in, const int* in_sizes, int n_in,
                              void* d_out, int out_size)
{
    const float* x      = (const float*)d_in[0];
    const float* loglam = (const float*)d_in[1];
    const float* Wd     = (const float*)d_in[2];
    const float* bd     = (const float*)d_in[3];
    const float* WB     = (const float*)d_in[4];
    const float* WC     = (const float*)d_in[5];
    const float* Wout   = (const float*)d_in[6];
    const float* bout   = (const float*)d_in[7];
    float* out          = (float*)d_out;

    float *p_delta, *p_Bt, *p_Ct, *p_hend, *p_D, *p_hstart;
    __nv_bfloat16 *p_xhi, *p_xlo, *p_Wdhi, *p_Wdlo;
    __half *p_Wouthi, *p_Woutlo, *p_flat;
    cudaGetSymbolAddress((void**)&p_delta,  g_delta);
    cudaGetSymbolAddress((void**)&p_Bt,     g_Bt);
    cudaGetSymbolAddress((void**)&p_Ct,     g_Ct);
    cudaGetSymbolAddress((void**)&p_hend,   g_hend);
    cudaGetSymbolAddress((void**)&p_D,      g_D);
    cudaGetSymbolAddress((void**)&p_hstart, g_hstart);
    cudaGetSymbolAddress((void**)&p_xhi,    g_xhi);
    cudaGetSymbolAddress((void**)&p_xlo,    g_xlo);
    cudaGetSymbolAddress((void**)&p_Wdhi,   g_Wdhi);
    cudaGetSymbolAddress((void**)&p_Wdlo,   g_Wdlo);
    cudaGetSymbolAddress((void**)&p_Wouthi, g_Wouthi);
    cudaGetSymbolAddress((void**)&p_Woutlo, g_Woutlo);
    cudaGetSymbolAddress((void**)&p_flat,   g_flat);

    cudaFuncSetAttribute(tgemm<true>, cudaFuncAttributeMaxDynamicSharedMemorySize, TG_SMEM);
    cudaFuncSetAttribute(tgemm_fp16,  cudaFuncAttributeMaxDynamicSharedMemorySize, TG2_SMEM);

    // splits
    {
        int n1 = MROWS * DMODEL;
        split_bf16<<<(n1 + 255) / 256, 256>>>(x, p_xhi, p_xlo, n1);
        int n2 = DMODEL * DMODEL;
        split_bf16<<<(n2 + 255) / 256, 256>>>(Wd, p_Wdhi, p_Wdlo, n2);
        int n3 = DMODEL * KFLAT;
        split_fp16<<<(n3 + 255) / 256, 256>>>(Wout, p_Wouthi, p_Woutlo, n3);
    }

    // 1. delta = softplus(x @ Wd^T + bd)   [4096 x 768], bf16 3-term
    tgemm<true><<<dim3(DMODEL / 96, MROWS / 128), 256, TG_SMEM>>>(
        p_xhi, p_xlo, p_Wdhi, p_Wdlo, bd, p_delta, DMODEL, DMODEL);

    // 2. Bt, Ct
    bc_kernel<<<MROWS, 256>>>(x, WB, WC, p_Bt, p_Ct);

    // 3. segmented scan -> flat fp16 [4096 x 12288]
    scan_a<<<(BATCH * NSEG * DN) / 256, 256>>>(p_delta, p_Bt, loglam, p_hend, p_D);
    scan_b<<<(BATCH * DN) / 256, 256>>>(p_hend, p_D, p_hstart);
    scan_c<<<(BATCH * NSEG * DN) / 256, 256>>>(p_delta, p_Bt, p_Ct, loglam,
                                               p_hstart, p_flat);

    // 4. out = flat @ (Wouthi+Woutlo)^T + bout   [4096 x 768], fp16 2-term
    tgemm_fp16<<<dim3(DMODEL / 96, MROWS / 128), 256, TG2_SMEM>>>(
        p_flat, p_Wouthi, p_Woutlo, bout, out, DMODEL, KFLAT);
}

// round 11
// speedup vs baseline: 7.3221x; 1.4934x over previous
#include <cuda_runtime.h>
#include <cuda_bf16.h>
#include <cuda_fp16.h>
#include <math.h>
#include <stdint.h>

#define BATCH  2
#define SEQLEN 2048
#define DMODEL 768
#define DSTATE 16
#define MROWS  (BATCH * SEQLEN)          // 4096
#define KFLAT  (DMODEL * DSTATE)         // 12288
#define NSEG   16
#define TSEG   (SEQLEN / NSEG)           // 128
#define DN     KFLAT                     // 12288 (d,n) pairs

// ---------------- scratch (device globals; no allocation allowed) ----------
__device__ float g_delta[(size_t)MROWS * DMODEL];
__device__ float g_Bt[(size_t)MROWS * DSTATE];
__device__ float g_Ct[(size_t)MROWS * DSTATE];
__device__ float g_hend[(size_t)BATCH * NSEG * DN];
__device__ float g_D[(size_t)BATCH * NSEG * DN];
__device__ float g_hstart[(size_t)BATCH * NSEG * DN];
__device__ __nv_bfloat16 g_xhi[(size_t)MROWS * DMODEL];
__device__ __nv_bfloat16 g_xlo[(size_t)MROWS * DMODEL];
__device__ __nv_bfloat16 g_Wdhi[(size_t)DMODEL * DMODEL];
__device__ __nv_bfloat16 g_Wdlo[(size_t)DMODEL * DMODEL];
__device__ __half g_Wouth[(size_t)DMODEL * KFLAT];        // single fp16 W
__device__ __half g_flat[(size_t)MROWS * KFLAT];          // single fp16 y

__device__ __forceinline__ float softplusf(float x) {
    if (x > 20.f) return x;
    return log1pf(__expf(x));
}

__device__ __forceinline__ uint32_t smem_u32(const void* p) {
    uint32_t a;
    asm("{ .reg .u64 t; cvta.to.shared.u64 t, %1; cvt.u32.u64 %0, t; }"
        : "=r"(a) : "l"(p));
    return a;
}

__device__ __forceinline__ void cp16(uint32_t dst, const void* src) {
    asm volatile("cp.async.cg.shared.global [%0], [%1], 16;"
                 :: "r"(dst), "l"(src) : "memory");
}

#define MMA16816BF(d, a0, a1, a2, a3, b0, b1)                                 \
    asm volatile(                                                             \
        "mma.sync.aligned.m16n8k16.row.col.f32.bf16.bf16.f32 "                \
        "{%0,%1,%2,%3},{%4,%5,%6,%7},{%8,%9},{%0,%1,%2,%3};"                  \
        : "+f"((d)[0]), "+f"((d)[1]), "+f"((d)[2]), "+f"((d)[3])              \
        : "r"(a0), "r"(a1), "r"(a2), "r"(a3), "r"(b0), "r"(b1))

#define MMA16816FP(d, a0, a1, a2, a3, b0, b1)                                 \
    asm volatile(                                                             \
        "mma.sync.aligned.m16n8k16.row.col.f32.f16.f16.f32 "                  \
        "{%0,%1,%2,%3},{%4,%5,%6,%7},{%8,%9},{%0,%1,%2,%3};"                  \
        : "+f"((d)[0]), "+f"((d)[1]), "+f"((d)[2]), "+f"((d)[3])              \
        : "r"(a0), "r"(a1), "r"(a2), "r"(a3), "r"(b0), "r"(b1))

#define LDSM4(r0, r1, r2, r3, addr)                                           \
    asm volatile("ldmatrix.sync.aligned.m8n8.x4.shared.b16 {%0,%1,%2,%3}, [%4];" \
                 : "=r"(r0), "=r"(r1), "=r"(r2), "=r"(r3) : "r"(addr))

#define LDSM2(r0, r1, addr)                                                   \
    asm volatile("ldmatrix.sync.aligned.m8n8.x2.shared.b16 {%0,%1}, [%2];"    \
                 : "=r"(r0), "=r"(r1) : "r"(addr))

// ---------------------------------------------------------------------------
// bf16 3-term GEMM (delta path; unchanged): BM=128, BN=96, BK=32, 3-stage,
// warp tile 64x24, 2 CTAs/SM.
// ---------------------------------------------------------------------------
#define BKB       64
#define ST_AHI    0
#define ST_ALO    8192
#define ST_BHI    16384
#define ST_BLO    22528
#define ST_BYTES  28672
#define TG_SMEM   (3 * ST_BYTES)

template <bool SP>
__global__ void __launch_bounds__(256, 2)
tgemm(const __nv_bfloat16* __restrict__ Ahi, const __nv_bfloat16* __restrict__ Alo,
      const __nv_bfloat16* __restrict__ Bhi, const __nv_bfloat16* __restrict__ Blo,
      const float* __restrict__ bias, float* __restrict__ C, int Nn, int K)
{
    extern __shared__ char dsm[];
    const uint32_t sb = smem_u32(dsm);
    const int t = threadIdx.x, wid = t >> 5, lane = t & 31;
    const int bm = blockIdx.y * 128, bn = blockIdx.x * 96;

    const size_t rs = (size_t)K * 2;
    const char* A0 = (const char*)Ahi + (size_t)bm * rs;
    const char* A1 = (const char*)Alo + (size_t)bm * rs;
    const char* B0 = (const char*)Bhi + (size_t)bn * rs;
    const char* B1 = (const char*)Blo + (size_t)bn * rs;

    const int nk = K / 32;
    const int lch  = t & 3;
    const int lrow = t >> 2;
    const int wm = wid >> 2, wn = wid & 3;
    const int mbase = wm * 64, nbase = wn * 24;

    float acc[4][3][4];
#pragma unroll
    for (int i = 0; i < 4; i++)
#pragma unroll
        for (int j = 0; j < 3; j++)
#pragma unroll
            for (int q = 0; q < 4; q++) acc[i][j][q] = 0.f;

    auto load_stage = [&](int kt) {
        const uint32_t st = sb + (kt % 3) * ST_BYTES;
        const size_t kb = (size_t)kt * BKB;
#pragma unroll
        for (int i = 0; i < 2; i++) {
            const int row = lrow + i * 64;
            const uint32_t sw = (lch ^ ((row >> 1) & 3)) * 16;
            const size_t go = (size_t)row * rs + kb + lch * 16;
            cp16(st + ST_AHI + row * 64 + sw, A0 + go);
            cp16(st + ST_ALO + row * 64 + sw, A1 + go);
        }
        {
            const int row = lrow;
            const uint32_t sw = (lch ^ ((row >> 1) & 3)) * 16;
            const size_t go = (size_t)row * rs + kb + lch * 16;
            cp16(st + ST_BHI + row * 64 + sw, B0 + go);
            cp16(st + ST_BLO + row * 64 + sw, B1 + go);
        }
        if (lrow < 32) {
            const int row = lrow + 64;
            const uint32_t sw = (lch ^ ((row >> 1) & 3)) * 16;
            const size_t go = (size_t)row * rs + kb + lch * 16;
            cp16(st + ST_BHI + row * 64 + sw, B0 + go);
            cp16(st + ST_BLO + row * 64 + sw, B1 + go);
        }
    };

    load_stage(0);
    asm volatile("cp.async.commit_group;" ::: "memory");
    load_stage(1);
    asm volatile("cp.async.commit_group;" ::: "memory");

    for (int kt = 0; kt < nk; kt++) {
        asm volatile("cp.async.wait_group 1;" ::: "memory");
        __syncthreads();
        if (kt + 2 < nk) load_stage(kt + 2);
        asm volatile("cp.async.commit_group;" ::: "memory");

        const uint32_t st = sb + (kt % 3) * ST_BYTES;
#pragma unroll
        for (int ks = 0; ks < 2; ks++) {
            uint32_t ah[4][4], al[4][4];
#pragma unroll
            for (int mt = 0; mt < 4; mt++) {
                const int arow = mbase + mt * 16 + (lane & 15);
                const int ac = (ks * 2 + (lane >> 4)) ^ ((arow >> 1) & 3);
                const uint32_t off = arow * 64 + ac * 16;
                LDSM4(ah[mt][0], ah[mt][1], ah[mt][2], ah[mt][3],
                      st + ST_AHI + off);
                LDSM4(al[mt][0], al[mt][1], al[mt][2], al[mt][3],
                      st + ST_ALO + off);
            }
            uint32_t bh[3][2], bl[3][2];
            {
                const int brow = nbase + ((lane >> 4) & 1) * 8 + (lane & 7);
                const int bc = (ks * 2 + ((lane >> 3) & 1)) ^ ((brow >> 1) & 3);
                const uint32_t off = brow * 64 + bc * 16;
                LDSM4(bh[0][0], bh[0][1], bh[1][0], bh[1][1], st + ST_BHI + off);
                LDSM4(bl[0][0], bl[0][1], bl[1][0], bl[1][1], st + ST_BLO + off);
            }
            {
                const int brow = nbase + 16 + (lane & 7);
                const int bc = (ks * 2 + ((lane >> 3) & 1)) ^ ((brow >> 1) & 3);
                const uint32_t off = brow * 64 + bc * 16;
                LDSM2(bh[2][0], bh[2][1], st + ST_BHI + off);
                LDSM2(bl[2][0], bl[2][1], st + ST_BLO + off);
            }
#pragma unroll
            for (int mt = 0; mt < 4; mt++)
#pragma unroll
                for (int nt = 0; nt < 3; nt++) {
                    MMA16816BF(acc[mt][nt], ah[mt][0], ah[mt][1], ah[mt][2],
                               ah[mt][3], bh[nt][0], bh[nt][1]);
                    MMA16816BF(acc[mt][nt], ah[mt][0], ah[mt][1], ah[mt][2],
                               ah[mt][3], bl[nt][0], bl[nt][1]);
                    MMA16816BF(acc[mt][nt], al[mt][0], al[mt][1], al[mt][2],
                               al[mt][3], bh[nt][0], bh[nt][1]);
                }
        }
    }

    __syncthreads();
#pragma unroll
    for (int mt = 0; mt < 4; mt++) {
        const int r0 = bm + mbase + mt * 16 + (lane >> 2);
#pragma unroll
        for (int nt = 0; nt < 3; nt++) {
            const int col = bn + nbase + nt * 8 + (lane & 3) * 2;
            const float b0 = __ldg(&bias[col]);
            const float b1 = __ldg(&bias[col + 1]);
            float2 v0, v1;
            v0.x = acc[mt][nt][0] + b0;
            v0.y = acc[mt][nt][1] + b1;
            v1.x = acc[mt][nt][2] + b0;
            v1.y = acc[mt][nt][3] + b1;
            if (SP) {
                v0.x = softplusf(v0.x); v0.y = softplusf(v0.y);
                v1.x = softplusf(v1.x); v1.y = softplusf(v1.y);
            }
            *(float2*)&C[(size_t)r0 * Nn + col]       = v0;
            *(float2*)&C[(size_t)(r0 + 8) * Nn + col] = v1;
        }
    }
}

// ---------------------------------------------------------------------------
// fp16 1-term GEMM (out path): A and B both single fp16.
// C = A*B^T + bias. BM=128, BN=96, BK=32, 4-stage, warp 64x24, 2 CTAs/SM.
// Stage: A 8K | B 6K = 14336 B. 4 stages = 57344 B.
// ---------------------------------------------------------------------------
#define S2_A      0
#define S2_B      8192
#define S2_BYTES  14336
#define TG2_SMEM  (4 * S2_BYTES)

__global__ void __launch_bounds__(256, 2)
tgemm_fp16(const __half* __restrict__ A, const __half* __restrict__ B,
           const float* __restrict__ bias, float* __restrict__ C,
           int Nn, int K)
{
    extern __shared__ char dsm[];
    const uint32_t sb = smem_u32(dsm);
    const int t = threadIdx.x, wid = t >> 5, lane = t & 31;
    const int bm = blockIdx.y * 128, bn = blockIdx.x * 96;

    const size_t rs = (size_t)K * 2;
    const char* Ag = (const char*)A + (size_t)bm * rs;
    const char* Bg = (const char*)B + (size_t)bn * rs;

    const int nk = K / 32;
    const int lch  = t & 3;
    const int lrow = t >> 2;
    const int wm = wid >> 2, wn = wid & 3;
    const int mbase = wm * 64, nbase = wn * 24;

    float acc[4][3][4];
#pragma unroll
    for (int i = 0; i < 4; i++)
#pragma unroll
        for (int j = 0; j < 3; j++)
#pragma unroll
            for (int q = 0; q < 4; q++) acc[i][j][q] = 0.f;

    auto load_stage = [&](int kt) {
        const uint32_t st = sb + (kt & 3) * S2_BYTES;
        const size_t kb = (size_t)kt * BKB;
#pragma unroll
        for (int i = 0; i < 2; i++) {
            const int row = lrow + i * 64;
            const uint32_t sw = (lch ^ ((row >> 1) & 3)) * 16;
            const size_t go = (size_t)row * rs + kb + lch * 16;
            cp16(st + S2_A + row * 64 + sw, Ag + go);
        }
        {
            const int row = lrow;
            const uint32_t sw = (lch ^ ((row >> 1) & 3)) * 16;
            const size_t go = (size_t)row * rs + kb + lch * 16;
            cp16(st + S2_B + row * 64 + sw, Bg + go);
        }
        if (lrow < 32) {
            const int row = lrow + 64;
            const uint32_t sw = (lch ^ ((row >> 1) & 3)) * 16;
            const size_t go = (size_t)row * rs + kb + lch * 16;
            cp16(st + S2_B + row * 64 + sw, Bg + go);
        }
    };

    load_stage(0);
    asm volatile("cp.async.commit_group;" ::: "memory");
    load_stage(1);
    asm volatile("cp.async.commit_group;" ::: "memory");
    load_stage(2);
    asm volatile("cp.async.commit_group;" ::: "memory");

    for (int kt = 0; kt < nk; kt++) {
        asm volatile("cp.async.wait_group 2;" ::: "memory");
        __syncthreads();
        if (kt + 3 < nk) load_stage(kt + 3);
        asm volatile("cp.async.commit_group;" ::: "memory");

        const uint32_t st = sb + (kt & 3) * S2_BYTES;
#pragma unroll
        for (int ks = 0; ks < 2; ks++) {
            uint32_t a[4][4];
#pragma unroll
            for (int mt = 0; mt < 4; mt++) {
                const int arow = mbase + mt * 16 + (lane & 15);
                const int ac = (ks * 2 + (lane >> 4)) ^ ((arow >> 1) & 3);
                const uint32_t off = arow * 64 + ac * 16;
                LDSM4(a[mt][0], a[mt][1], a[mt][2], a[mt][3], st + S2_A + off);
            }
            uint32_t b[3][2];
            {
                const int brow = nbase + ((lane >> 4) & 1) * 8 + (lane & 7);
                const int bc = (ks * 2 + ((lane >> 3) & 1)) ^ ((brow >> 1) & 3);
                const uint32_t off = brow * 64 + bc * 16;
                LDSM4(b[0][0], b[0][1], b[1][0], b[1][1], st + S2_B + off);
            }
            {
                const int brow = nbase + 16 + (lane & 7);
                const int bc = (ks * 2 + ((lane >> 3) & 1)) ^ ((brow >> 1) & 3);
                const uint32_t off = brow * 64 + bc * 16;
                LDSM2(b[2][0], b[2][1], st + S2_B + off);
            }
#pragma unroll
            for (int mt = 0; mt < 4; mt++)
#pragma unroll
                for (int nt = 0; nt < 3; nt++)
                    MMA16816FP(acc[mt][nt], a[mt][0], a[mt][1], a[mt][2],
                               a[mt][3], b[nt][0], b[nt][1]);
        }
    }

    __syncthreads();
#pragma unroll
    for (int mt = 0; mt < 4; mt++) {
        const int r0 = bm + mbase + mt * 16 + (lane >> 2);
#pragma unroll
        for (int nt = 0; nt < 3; nt++) {
            const int col = bn + nbase + nt * 8 + (lane & 3) * 2;
            const float b0 = __ldg(&bias[col]);
            const float b1 = __ldg(&bias[col + 1]);
            float2 v0, v1;
            v0.x = acc[mt][nt][0] + b0;
            v0.y = acc[mt][nt][1] + b1;
            v1.x = acc[mt][nt][2] + b0;
            v1.y = acc[mt][nt][3] + b1;
            *(float2*)&C[(size_t)r0 * Nn + col]       = v0;
            *(float2*)&C[(size_t)(r0 + 8) * Nn + col] = v1;
        }
    }
}

// ---------------------------------------------------------------------------
// fp32 -> bf16 hi/lo split (delta-path operands)
// ---------------------------------------------------------------------------
__global__ void __launch_bounds__(256)
split_bf16(const float* __restrict__ in, __nv_bfloat16* __restrict__ hi,
           __nv_bfloat16* __restrict__ lo, int n)
{
    int i = blockIdx.x * 256 + threadIdx.x;
    if (i < n) {
        float v = in[i];
        __nv_bfloat16 h = __float2bfloat16(v);
        hi[i] = h;
        lo[i] = __float2bfloat16(v - __bfloat162float(h));
    }
}

// fp32 -> fp16 (Wout, single term)
__global__ void __launch_bounds__(256)
to_fp16(const float* __restrict__ in, __half* __restrict__ o, int n)
{
    int i = blockIdx.x * 256 + threadIdx.x;
    if (i < n) o[i] = __float2half_rn(in[i]);
}

// ---------------------------------------------------------------------------
// Bt / Ct: per-row GEMV onto 16+16 outputs. One block per row.
// ---------------------------------------------------------------------------
__global__ void __launch_bounds__(256)
bc_kernel(const float* __restrict__ x, const float* __restrict__ WB,
          const float* __restrict__ WC, float* __restrict__ Bt,
          float* __restrict__ Ct)
{
    __shared__ float xs[DMODEL];
    const int row = blockIdx.x;
    const int t = threadIdx.x;
    for (int i = t; i < DMODEL; i += 256)
        xs[i] = x[(size_t)row * DMODEL + i];
    __syncthreads();

    const int warp = t >> 5;
    const int lane = t & 31;
#pragma unroll
    for (int o = 0; o < 4; o++) {
        const int j = warp * 4 + o;
        const float* W = (j < DSTATE) ? (WB + (size_t)j * DMODEL)
                                      : (WC + (size_t)(j - DSTATE) * DMODEL);
        float s = 0.f;
#pragma unroll 4
        for (int k = lane; k < DMODEL; k += 32)
            s = fmaf(xs[k], W[k], s);
#pragma unroll
        for (int off = 16; off; off >>= 1)
            s += __shfl_xor_sync(0xffffffffu, s, off);
        if (lane == 0) {
            if (j < DSTATE) Bt[(size_t)row * DSTATE + j] = s;
            else            Ct[(size_t)row * DSTATE + (j - DSTATE)] = s;
        }
    }
}

// ---------------------------------------------------------------------------
// Segmented scan, phase A: per (b,seg,d,n) carry + decay.
// ---------------------------------------------------------------------------
__global__ void __launch_bounds__(256)
scan_a(const float* __restrict__ delta, const float* __restrict__ Btg,
       const float* __restrict__ loglam, float* __restrict__ hend,
       float* __restrict__ Dg)
{
    const int tid = blockIdx.x * 256 + threadIdx.x;
    const int b   = tid / (NSEG * DN);
    const int rem = tid % (NSEG * DN);
    const int seg = rem / DN;
    const int r   = rem % DN;
    const int d   = r / DSTATE;
    const int n   = r % DSTATE;

    const float lam = softplusf(loglam[r]);
    const int l0 = seg * TSEG;

    const float* dp = delta + ((size_t)b * SEQLEN + l0) * DMODEL + d;
    const float* bp = Btg + ((size_t)b * SEQLEN + l0) * DSTATE + n;

    float h = 0.f, sd = 0.f;
#pragma unroll 4
    for (int l = 0; l < TSEG; l++) {
        const float dl = __ldg(dp); dp += DMODEL;
        const float bt = __ldg(bp); bp += DSTATE;
        const float a = __expf(-dl * lam);
        h = fmaf(a, h, dl * bt);
        sd += dl;
    }
    hend[tid] = h;
    Dg[tid] = __expf(-sd * lam);
}

// Phase B: propagate carries across NSEG segments.
__global__ void __launch_bounds__(256)
scan_b(const float* __restrict__ hend, const float* __restrict__ Dg,
       float* __restrict__ hstart)
{
    const int tid = blockIdx.x * 256 + threadIdx.x;
    const int b = tid / DN;
    const int r = tid % DN;

    float h = 0.f;
#pragma unroll
    for (int s = 0; s < NSEG; s++) {
        const size_t idx = ((size_t)b * NSEG + s) * DN + r;
        hstart[idx] = h;
        h = fmaf(Dg[idx], h, hend[idx]);
    }
}

// Phase C: re-run segments from h_start, write y as single fp16.
__global__ void __launch_bounds__(256)
scan_c(const float* __restrict__ delta, const float* __restrict__ Btg,
       const float* __restrict__ Ctg, const float* __restrict__ loglam,
       const float* __restrict__ hstart, __half* __restrict__ yflat)
{
    const int tid = blockIdx.x * 256 + threadIdx.x;
    const int b   = tid / (NSEG * DN);
    const int rem = tid % (NSEG * DN);
    const int seg = rem / DN;
    const int r   = rem % DN;
    const int d   = r / DSTATE;
    const int n   = r % DSTATE;

    const float lam = softplusf(loglam[r]);
    const int l0 = seg * TSEG;

    const float* dp = delta + ((size_t)b * SEQLEN + l0) * DMODEL + d;
    const float* bp = Btg + ((size_t)b * SEQLEN + l0) * DSTATE + n;
    const float* cp = Ctg + ((size_t)b * SEQLEN + l0) * DSTATE + n;
    __half* yp = yflat + ((size_t)b * SEQLEN + l0) * KFLAT + r;

    float h = hstart[tid];
#pragma unroll 4
    for (int l = 0; l < TSEG; l++) {
        const float dl = __ldg(dp); dp += DMODEL;
        const float bt = __ldg(bp); bp += DSTATE;
        const float ct = __ldg(cp); cp += DSTATE;
        const float a = __expf(-dl * lam);
        h = fmaf(a, h, dl * bt);
        *yp = __float2half_rn(h * ct);
        yp += KFLAT;
    }
}

// ---------------------------------------------------------------------------
extern "C" void kernel_launch(void* const* d_in, const int* in_sizes, int n_in,
                              void* d_out, int out_size)
{
    const float* x      = (const float*)d_in[0];
    const float* loglam = (const float*)d_in[1];
    const float* Wd     = (const float*)d_in[2];
    const float* bd     = (const float*)d_in[3];
    const float* WB     = (const float*)d_in[4];
    const float* WC     = (const float*)d_in[5];
    const float* Wout   = (const float*)d_in[6];
    const float* bout   = (const float*)d_in[7];
    float* out          = (float*)d_out;

    float *p_delta, *p_Bt, *p_Ct, *p_hend, *p_D, *p_hstart;
    __nv_bfloat16 *p_xhi, *p_xlo, *p_Wdhi, *p_Wdlo;
    __half *p_Wouth, *p_flat;
    cudaGetSymbolAddress((void**)&p_delta,  g_delta);
    cudaGetSymbolAddress((void**)&p_Bt,     g_Bt);
    cudaGetSymbolAddress((void**)&p_Ct,     g_Ct);
    cudaGetSymbolAddress((void**)&p_hend,   g_hend);
    cudaGetSymbolAddress((void**)&p_D,      g_D);
    cudaGetSymbolAddress((void**)&p_hstart, g_hstart);
    cudaGetSymbolAddress((void**)&p_xhi,    g_xhi);
    cudaGetSymbolAddress((void**)&p_xlo,    g_xlo);
    cudaGetSymbolAddress((void**)&p_Wdhi,   g_Wdhi);
    cudaGetSymbolAddress((void**)&p_Wdlo,   g_Wdlo);
    cudaGetSymbolAddress((void**)&p_Wouth,  g_Wouth);
    cudaGetSymbolAddress((void**)&p_flat,   g_flat);

    cudaFuncSetAttribute(tgemm<true>, cudaFuncAttributeMaxDynamicSharedMemorySize, TG_SMEM);
    cudaFuncSetAttribute(tgemm_fp16,  cudaFuncAttributeMaxDynamicSharedMemorySize, TG2_SMEM);

    // splits / conversions
    {
        int n1 = MROWS * DMODEL;
        split_bf16<<<(n1 + 255) / 256, 256>>>(x, p_xhi, p_xlo, n1);
        int n2 = DMODEL * DMODEL;
        split_bf16<<<(n2 + 255) / 256, 256>>>(Wd, p_Wdhi, p_Wdlo, n2);
        int n3 = DMODEL * KFLAT;
        to_fp16<<<(n3 + 255) / 256, 256>>>(Wout, p_Wouth, n3);
    }

    // 1. delta = softplus(x @ Wd^T + bd)   [4096 x 768], bf16 3-term
    tgemm<true><<<dim3(DMODEL / 96, MROWS / 128), 256, TG_SMEM>>>(
        p_xhi, p_xlo, p_Wdhi, p_Wdlo, bd, p_delta, DMODEL, DMODEL);

    // 2. Bt, Ct
    bc_kernel<<<MROWS, 256>>>(x, WB, WC, p_Bt, p_Ct);

    // 3. segmented scan -> flat fp16 [4096 x 12288]
    scan_a<<<(BATCH * NSEG * DN) / 256, 256>>>(p_delta, p_Bt, loglam, p_hend, p_D);
    scan_b<<<(BATCH * DN) / 256, 256>>>(p_hend, p_D, p_hstart);
    scan_c<<<(BATCH * NSEG * DN) / 256, 256>>>(p_delta, p_Bt, p_Ct, loglam,
                                               p_hstart, p_flat);

    // 4. out = flat @ Wouth^T + bout   [4096 x 768], fp16 1-term
    tgemm_fp16<<<dim3(DMODEL / 96, MROWS / 128), 256, TG2_SMEM>>>(
        p_flat, p_Wouth, bout, out, DMODEL, KFLAT);
}

// round 12
// speedup vs baseline: 7.4548x; 1.0181x over previous
#include <cuda_runtime.h>
#include <cuda_fp16.h>
#include <math.h>
#include <stdint.h>

#define BATCH  2
#define SEQLEN 2048
#define DMODEL 768
#define DSTATE 16
#define MROWS  (BATCH * SEQLEN)          // 4096
#define KFLAT  (DMODEL * DSTATE)         // 12288
#define NSEG   64
#define TSEG   (SEQLEN / NSEG)           // 32
#define DN     KFLAT                     // 12288 (d,n) pairs

// ---------------- scratch (device globals; no allocation allowed) ----------
__device__ float g_delta[(size_t)MROWS * DMODEL];
__device__ float g_Bt[(size_t)MROWS * DSTATE];
__device__ float g_Ct[(size_t)MROWS * DSTATE];
__device__ float g_hend[(size_t)BATCH * NSEG * DN];
__device__ float g_D[(size_t)BATCH * NSEG * DN];
__device__ float g_hstart[(size_t)BATCH * NSEG * DN];
__device__ __half g_xhi[(size_t)MROWS * DMODEL];
__device__ __half g_xlo[(size_t)MROWS * DMODEL];
__device__ __half g_Wd16[(size_t)DMODEL * DMODEL];
__device__ __half g_Wouth[(size_t)DMODEL * KFLAT];
__device__ __half g_flat[(size_t)MROWS * KFLAT];

__device__ __forceinline__ float softplusf(float x) {
    if (x > 20.f) return x;
    return log1pf(__expf(x));
}

__device__ __forceinline__ uint32_t smem_u32(const void* p) {
    uint32_t a;
    asm("{ .reg .u64 t; cvta.to.shared.u64 t, %1; cvt.u32.u64 %0, t; }"
        : "=r"(a) : "l"(p));
    return a;
}

__device__ __forceinline__ void cp16(uint32_t dst, const void* src) {
    asm volatile("cp.async.cg.shared.global [%0], [%1], 16;"
                 :: "r"(dst), "l"(src) : "memory");
}

#define MMA16816FP(d, a0, a1, a2, a3, b0, b1)                                 \
    asm volatile(                                                             \
        "mma.sync.aligned.m16n8k16.row.col.f32.f16.f16.f32 "                  \
        "{%0,%1,%2,%3},{%4,%5,%6,%7},{%8,%9},{%0,%1,%2,%3};"                  \
        : "+f"((d)[0]), "+f"((d)[1]), "+f"((d)[2]), "+f"((d)[3])              \
        : "r"(a0), "r"(a1), "r"(a2), "r"(a3), "r"(b0), "r"(b1))

#define LDSM4(r0, r1, r2, r3, addr)                                           \
    asm volatile("ldmatrix.sync.aligned.m8n8.x4.shared.b16 {%0,%1,%2,%3}, [%4];" \
                 : "=r"(r0), "=r"(r1), "=r"(r2), "=r"(r3) : "r"(addr))

#define LDSM2(r0, r1, addr)                                                   \
    asm volatile("ldmatrix.sync.aligned.m8n8.x2.shared.b16 {%0,%1}, [%2];"    \
                 : "=r"(r0), "=r"(r1) : "r"(addr))

#define BKB 64

// ---------------------------------------------------------------------------
// fp16 2-term GEMM (delta path): A = x hi/lo fp16, B = Wd single fp16.
// C = softplus((Ahi+Alo)*B^T + bias). BM=128, BN=96, BK=32, 3-stage,
// warp 64x24, 2 CTAs/SM. Stage: Ahi 8K | Alo 8K | B 6K = 22528 B.
// ---------------------------------------------------------------------------
#define D2_AHI    0
#define D2_ALO    8192
#define D2_B      16384
#define D2_BYTES  22528
#define D2_SMEM   (3 * D2_BYTES)

__global__ void __launch_bounds__(256, 2)
tgemm_d2(const __half* __restrict__ Ahi, const __half* __restrict__ Alo,
         const __half* __restrict__ B, const float* __restrict__ bias,
         float* __restrict__ C, int Nn, int K)
{
    extern __shared__ char dsm[];
    const uint32_t sb = smem_u32(dsm);
    const int t = threadIdx.x, wid = t >> 5, lane = t & 31;
    const int bm = blockIdx.y * 128, bn = blockIdx.x * 96;

    const size_t rs = (size_t)K * 2;
    const char* A0 = (const char*)Ahi + (size_t)bm * rs;
    const char* A1 = (const char*)Alo + (size_t)bm * rs;
    const char* Bg = (const char*)B + (size_t)bn * rs;

    const int nk = K / 32;
    const int lch  = t & 3;
    const int lrow = t >> 2;
    const int wm = wid >> 2, wn = wid & 3;
    const int mbase = wm * 64, nbase = wn * 24;

    float acc[4][3][4];
#pragma unroll
    for (int i = 0; i < 4; i++)
#pragma unroll
        for (int j = 0; j < 3; j++)
#pragma unroll
            for (int q = 0; q < 4; q++) acc[i][j][q] = 0.f;

    auto load_stage = [&](int kt) {
        const uint32_t st = sb + (kt % 3) * D2_BYTES;
        const size_t kb = (size_t)kt * BKB;
#pragma unroll
        for (int i = 0; i < 2; i++) {
            const int row = lrow + i * 64;
            const uint32_t sw = (lch ^ ((row >> 1) & 3)) * 16;
            const size_t go = (size_t)row * rs + kb + lch * 16;
            cp16(st + D2_AHI + row * 64 + sw, A0 + go);
            cp16(st + D2_ALO + row * 64 + sw, A1 + go);
        }
        {
            const int row = lrow;
            const uint32_t sw = (lch ^ ((row >> 1) & 3)) * 16;
            const size_t go = (size_t)row * rs + kb + lch * 16;
            cp16(st + D2_B + row * 64 + sw, Bg + go);
        }
        if (lrow < 32) {
            const int row = lrow + 64;
            const uint32_t sw = (lch ^ ((row >> 1) & 3)) * 16;
            const size_t go = (size_t)row * rs + kb + lch * 16;
            cp16(st + D2_B + row * 64 + sw, Bg + go);
        }
    };

    load_stage(0);
    asm volatile("cp.async.commit_group;" ::: "memory");
    load_stage(1);
    asm volatile("cp.async.commit_group;" ::: "memory");

    for (int kt = 0; kt < nk; kt++) {
        asm volatile("cp.async.wait_group 1;" ::: "memory");
        __syncthreads();
        if (kt + 2 < nk) load_stage(kt + 2);
        asm volatile("cp.async.commit_group;" ::: "memory");

        const uint32_t st = sb + (kt % 3) * D2_BYTES;
#pragma unroll
        for (int ks = 0; ks < 2; ks++) {
            uint32_t ah[4][4], al[4][4];
#pragma unroll
            for (int mt = 0; mt < 4; mt++) {
                const int arow = mbase + mt * 16 + (lane & 15);
                const int ac = (ks * 2 + (lane >> 4)) ^ ((arow >> 1) & 3);
                const uint32_t off = arow * 64 + ac * 16;
                LDSM4(ah[mt][0], ah[mt][1], ah[mt][2], ah[mt][3],
                      st + D2_AHI + off);
                LDSM4(al[mt][0], al[mt][1], al[mt][2], al[mt][3],
                      st + D2_ALO + off);
            }
            uint32_t b[3][2];
            {
                const int brow = nbase + ((lane >> 4) & 1) * 8 + (lane & 7);
                const int bc = (ks * 2 + ((lane >> 3) & 1)) ^ ((brow >> 1) & 3);
                const uint32_t off = brow * 64 + bc * 16;
                LDSM4(b[0][0], b[0][1], b[1][0], b[1][1], st + D2_B + off);
            }
            {
                const int brow = nbase + 16 + (lane & 7);
                const int bc = (ks * 2 + ((lane >> 3) & 1)) ^ ((brow >> 1) & 3);
                const uint32_t off = brow * 64 + bc * 16;
                LDSM2(b[2][0], b[2][1], st + D2_B + off);
            }
#pragma unroll
            for (int mt = 0; mt < 4; mt++)
#pragma unroll
                for (int nt = 0; nt < 3; nt++) {
                    MMA16816FP(acc[mt][nt], ah[mt][0], ah[mt][1], ah[mt][2],
                               ah[mt][3], b[nt][0], b[nt][1]);
                    MMA16816FP(acc[mt][nt], al[mt][0], al[mt][1], al[mt][2],
                               al[mt][3], b[nt][0], b[nt][1]);
                }
        }
    }

    __syncthreads();
#pragma unroll
    for (int mt = 0; mt < 4; mt++) {
        const int r0 = bm + mbase + mt * 16 + (lane >> 2);
#pragma unroll
        for (int nt = 0; nt < 3; nt++) {
            const int col = bn + nbase + nt * 8 + (lane & 3) * 2;
            const float b0 = __ldg(&bias[col]);
            const float b1 = __ldg(&bias[col + 1]);
            float2 v0, v1;
            v0.x = softplusf(acc[mt][nt][0] + b0);
            v0.y = softplusf(acc[mt][nt][1] + b1);
            v1.x = softplusf(acc[mt][nt][2] + b0);
            v1.y = softplusf(acc[mt][nt][3] + b1);
            *(float2*)&C[(size_t)r0 * Nn + col]       = v0;
            *(float2*)&C[(size_t)(r0 + 8) * Nn + col] = v1;
        }
    }
}

// ---------------------------------------------------------------------------
// fp16 1-term GEMM (out path; unchanged from R11).
// ---------------------------------------------------------------------------
#define S2_A      0
#define S2_B      8192
#define S2_BYTES  14336
#define TG2_SMEM  (4 * S2_BYTES)

__global__ void __launch_bounds__(256, 2)
tgemm_fp16(const __half* __restrict__ A, const __half* __restrict__ B,
           const float* __restrict__ bias, float* __restrict__ C,
           int Nn, int K)
{
    extern __shared__ char dsm[];
    const uint32_t sb = smem_u32(dsm);
    const int t = threadIdx.x, wid = t >> 5, lane = t & 31;
    const int bm = blockIdx.y * 128, bn = blockIdx.x * 96;

    const size_t rs = (size_t)K * 2;
    const char* Ag = (const char*)A + (size_t)bm * rs;
    const char* Bg = (const char*)B + (size_t)bn * rs;

    const int nk = K / 32;
    const int lch  = t & 3;
    const int lrow = t >> 2;
    const int wm = wid >> 2, wn = wid & 3;
    const int mbase = wm * 64, nbase = wn * 24;

    float acc[4][3][4];
#pragma unroll
    for (int i = 0; i < 4; i++)
#pragma unroll
        for (int j = 0; j < 3; j++)
#pragma unroll
            for (int q = 0; q < 4; q++) acc[i][j][q] = 0.f;

    auto load_stage = [&](int kt) {
        const uint32_t st = sb + (kt & 3) * S2_BYTES;
        const size_t kb = (size_t)kt * BKB;
#pragma unroll
        for (int i = 0; i < 2; i++) {
            const int row = lrow + i * 64;
            const uint32_t sw = (lch ^ ((row >> 1) & 3)) * 16;
            const size_t go = (size_t)row * rs + kb + lch * 16;
            cp16(st + S2_A + row * 64 + sw, Ag + go);
        }
        {
            const int row = lrow;
            const uint32_t sw = (lch ^ ((row >> 1) & 3)) * 16;
            const size_t go = (size_t)row * rs + kb + lch * 16;
            cp16(st + S2_B + row * 64 + sw, Bg + go);
        }
        if (lrow < 32) {
            const int row = lrow + 64;
            const uint32_t sw = (lch ^ ((row >> 1) & 3)) * 16;
            const size_t go = (size_t)row * rs + kb + lch * 16;
            cp16(st + S2_B + row * 64 + sw, Bg + go);
        }
    };

    load_stage(0);
    asm volatile("cp.async.commit_group;" ::: "memory");
    load_stage(1);
    asm volatile("cp.async.commit_group;" ::: "memory");
    load_stage(2);
    asm volatile("cp.async.commit_group;" ::: "memory");

    for (int kt = 0; kt < nk; kt++) {
        asm volatile("cp.async.wait_group 2;" ::: "memory");
        __syncthreads();
        if (kt + 3 < nk) load_stage(kt + 3);
        asm volatile("cp.async.commit_group;" ::: "memory");

        const uint32_t st = sb + (kt & 3) * S2_BYTES;
#pragma unroll
        for (int ks = 0; ks < 2; ks++) {
            uint32_t a[4][4];
#pragma unroll
            for (int mt = 0; mt < 4; mt++) {
                const int arow = mbase + mt * 16 + (lane & 15);
                const int ac = (ks * 2 + (lane >> 4)) ^ ((arow >> 1) & 3);
                const uint32_t off = arow * 64 + ac * 16;
                LDSM4(a[mt][0], a[mt][1], a[mt][2], a[mt][3], st + S2_A + off);
            }
            uint32_t b[3][2];
            {
                const int brow = nbase + ((lane >> 4) & 1) * 8 + (lane & 7);
                const int bc = (ks * 2 + ((lane >> 3) & 1)) ^ ((brow >> 1) & 3);
                const uint32_t off = brow * 64 + bc * 16;
                LDSM4(b[0][0], b[0][1], b[1][0], b[1][1], st + S2_B + off);
            }
            {
                const int brow = nbase + 16 + (lane & 7);
                const int bc = (ks * 2 + ((lane >> 3) & 1)) ^ ((brow >> 1) & 3);
                const uint32_t off = brow * 64 + bc * 16;
                LDSM2(b[2][0], b[2][1], st + S2_B + off);
            }
#pragma unroll
            for (int mt = 0; mt < 4; mt++)
#pragma unroll
                for (int nt = 0; nt < 3; nt++)
                    MMA16816FP(acc[mt][nt], a[mt][0], a[mt][1], a[mt][2],
                               a[mt][3], b[nt][0], b[nt][1]);
        }
    }

    __syncthreads();
#pragma unroll
    for (int mt = 0; mt < 4; mt++) {
        const int r0 = bm + mbase + mt * 16 + (lane >> 2);
#pragma unroll
        for (int nt = 0; nt < 3; nt++) {
            const int col = bn + nbase + nt * 8 + (lane & 3) * 2;
            const float b0 = __ldg(&bias[col]);
            const float b1 = __ldg(&bias[col + 1]);
            float2 v0, v1;
            v0.x = acc[mt][nt][0] + b0;
            v0.y = acc[mt][nt][1] + b1;
            v1.x = acc[mt][nt][2] + b0;
            v1.y = acc[mt][nt][3] + b1;
            *(float2*)&C[(size_t)r0 * Nn + col]       = v0;
            *(float2*)&C[(size_t)(r0 + 8) * Nn + col] = v1;
        }
    }
}

// ---------------------------------------------------------------------------
// fp32 -> fp16 hi/lo split (x) and single fp16 (weights)
// ---------------------------------------------------------------------------
__global__ void __launch_bounds__(256)
split_x16(const float* __restrict__ in, __half* __restrict__ hi,
          __half* __restrict__ lo, int n)
{
    int i = blockIdx.x * 256 + threadIdx.x;
    if (i < n) {
        float v = in[i];
        __half h = __float2half_rn(v);
        hi[i] = h;
        lo[i] = __float2half_rn(v - __half2float(h));
    }
}

__global__ void __launch_bounds__(256)
to_fp16(const float* __restrict__ in, __half* __restrict__ o, int n)
{
    int i = blockIdx.x * 256 + threadIdx.x;
    if (i < n) o[i] = __float2half_rn(in[i]);
}

// ---------------------------------------------------------------------------
// Bt / Ct: per-row GEMV onto 16+16 outputs. One block per row.
// ---------------------------------------------------------------------------
__global__ void __launch_bounds__(256)
bc_kernel(const float* __restrict__ x, const float* __restrict__ WB,
          const float* __restrict__ WC, float* __restrict__ Bt,
          float* __restrict__ Ct)
{
    __shared__ float xs[DMODEL];
    const int row = blockIdx.x;
    const int t = threadIdx.x;
    for (int i = t; i < DMODEL; i += 256)
        xs[i] = x[(size_t)row * DMODEL + i];
    __syncthreads();

    const int warp = t >> 5;
    const int lane = t & 31;
#pragma unroll
    for (int o = 0; o < 4; o++) {
        const int j = warp * 4 + o;
        const float* W = (j < DSTATE) ? (WB + (size_t)j * DMODEL)
                                      : (WC + (size_t)(j - DSTATE) * DMODEL);
        float s = 0.f;
#pragma unroll 4
        for (int k = lane; k < DMODEL; k += 32)
            s = fmaf(xs[k], W[k], s);
#pragma unroll
        for (int off = 16; off; off >>= 1)
            s += __shfl_xor_sync(0xffffffffu, s, off);
        if (lane == 0) {
            if (j < DSTATE) Bt[(size_t)row * DSTATE + j] = s;
            else            Ct[(size_t)row * DSTATE + (j - DSTATE)] = s;
        }
    }
}

// ---------------------------------------------------------------------------
// Segmented scan, phase A: one thread per (b,seg,d), 16 n-states in regs.
// ---------------------------------------------------------------------------
__global__ void __launch_bounds__(256)
scan_a(const float* __restrict__ delta, const float* __restrict__ Btg,
       const float* __restrict__ loglam, float* __restrict__ hend,
       float* __restrict__ Dg)
{
    const int tid = blockIdx.x * 256 + threadIdx.x;   // < BATCH*NSEG*DMODEL
    const int b   = tid / (NSEG * DMODEL);
    const int rem = tid % (NSEG * DMODEL);
    const int seg = rem / DMODEL;
    const int d   = rem % DMODEL;

    float lam[16];
    {
        const float4* lp = (const float4*)(loglam + d * DSTATE);
#pragma unroll
        for (int i = 0; i < 4; i++) {
            float4 v = __ldg(lp + i);
            lam[i * 4 + 0] = softplusf(v.x);
            lam[i * 4 + 1] = softplusf(v.y);
            lam[i * 4 + 2] = softplusf(v.z);
            lam[i * 4 + 3] = softplusf(v.w);
        }
    }

    const float* dp = delta + ((size_t)b * SEQLEN + seg * TSEG) * DMODEL + d;
    const float4* bp = (const float4*)(Btg + ((size_t)b * SEQLEN + seg * TSEG) * DSTATE);

    float h[16];
#pragma unroll
    for (int n = 0; n < 16; n++) h[n] = 0.f;
    float sd = 0.f;

    for (int l = 0; l < TSEG; l++) {
        const float dl = __ldg(dp); dp += DMODEL;
        float bt[16];
#pragma unroll
        for (int i = 0; i < 4; i++) {
            float4 v = __ldg(bp + i);
            bt[i * 4 + 0] = v.x; bt[i * 4 + 1] = v.y;
            bt[i * 4 + 2] = v.z; bt[i * 4 + 3] = v.w;
        }
        bp += 4;
#pragma unroll
        for (int n = 0; n < 16; n++) {
            const float a = __expf(-dl * lam[n]);
            h[n] = fmaf(a, h[n], dl * bt[n]);
        }
        sd += dl;
    }

    const size_t base = ((size_t)b * NSEG + seg) * DN + (size_t)d * DSTATE;
    float4* he = (float4*)(hend + base);
    float4* dg = (float4*)(Dg + base);
#pragma unroll
    for (int i = 0; i < 4; i++) {
        he[i] = make_float4(h[i * 4], h[i * 4 + 1], h[i * 4 + 2], h[i * 4 + 3]);
        dg[i] = make_float4(__expf(-sd * lam[i * 4]),
                            __expf(-sd * lam[i * 4 + 1]),
                            __expf(-sd * lam[i * 4 + 2]),
                            __expf(-sd * lam[i * 4 + 3]));
    }
}

// Phase B: propagate carries across NSEG segments.
__global__ void __launch_bounds__(256)
scan_b(const float* __restrict__ hend, const float* __restrict__ Dg,
       float* __restrict__ hstart)
{
    const int tid = blockIdx.x * 256 + threadIdx.x;   // < BATCH*DN
    const int b = tid / DN;
    const int r = tid % DN;

    float h = 0.f;
    for (int s = 0; s < NSEG; s++) {
        const size_t idx = ((size_t)b * NSEG + s) * DN + r;
        hstart[idx] = h;
        h = fmaf(Dg[idx], h, hend[idx]);
    }
}

// Phase C: one thread per (b,seg,d); re-run from h_start, write y fp16.
__global__ void __launch_bounds__(256)
scan_c(const float* __restrict__ delta, const float* __restrict__ Btg,
       const float* __restrict__ Ctg, const float* __restrict__ loglam,
       const float* __restrict__ hstart, __half* __restrict__ yflat)
{
    const int tid = blockIdx.x * 256 + threadIdx.x;   // < BATCH*NSEG*DMODEL
    const int b   = tid / (NSEG * DMODEL);
    const int rem = tid % (NSEG * DMODEL);
    const int seg = rem / DMODEL;
    const int d   = rem % DMODEL;

    float lam[16];
    {
        const float4* lp = (const float4*)(loglam + d * DSTATE);
#pragma unroll
        for (int i = 0; i < 4; i++) {
            float4 v = __ldg(lp + i);
            lam[i * 4 + 0] = softplusf(v.x);
            lam[i * 4 + 1] = softplusf(v.y);
            lam[i * 4 + 2] = softplusf(v.z);
            lam[i * 4 + 3] = softplusf(v.w);
        }
    }

    const float* dp = delta + ((size_t)b * SEQLEN + seg * TSEG) * DMODEL + d;
    const float4* bp = (const float4*)(Btg + ((size_t)b * SEQLEN + seg * TSEG) * DSTATE);
    const float4* cp = (const float4*)(Ctg + ((size_t)b * SEQLEN + seg * TSEG) * DSTATE);
    __half* yp = yflat + ((size_t)b * SEQLEN + seg * TSEG) * KFLAT + (size_t)d * DSTATE;

    float h[16];
    {
        const size_t base = ((size_t)b * NSEG + seg) * DN + (size_t)d * DSTATE;
        const float4* hs = (const float4*)(hstart + base);
#pragma unroll
        for (int i = 0; i < 4; i++) {
            float4 v = hs[i];
            h[i * 4 + 0] = v.x; h[i * 4 + 1] = v.y;
            h[i * 4 + 2] = v.z; h[i * 4 + 3] = v.w;
        }
    }

    for (int l = 0; l < TSEG; l++) {
        const float dl = __ldg(dp); dp += DMODEL;
        float bt[16], ct[16];
#pragma unroll
        for (int i = 0; i < 4; i++) {
            float4 v = __ldg(bp + i);
            bt[i * 4 + 0] = v.x; bt[i * 4 + 1] = v.y;
            bt[i * 4 + 2] = v.z; bt[i * 4 + 3] = v.w;
            float4 w = __ldg(cp + i);
            ct[i * 4 + 0] = w.x; ct[i * 4 + 1] = w.y;
            ct[i * 4 + 2] = w.z; ct[i * 4 + 3] = w.w;
        }
        bp += 4; cp += 4;

        uint32_t pk[8];
#pragma unroll
        for (int n = 0; n < 16; n++) {
            const float a = __expf(-dl * lam[n]);
            h[n] = fmaf(a, h[n], dl * bt[n]);
        }
#pragma unroll
        for (int i = 0; i < 8; i++) {
            __half2 v = __floats2half2_rn(h[i * 2] * ct[i * 2],
                                          h[i * 2 + 1] * ct[i * 2 + 1]);
            pk[i] = *(uint32_t*)&v;
        }
        uint4* yo = (uint4*)yp;
        yo[0] = make_uint4(pk[0], pk[1], pk[2], pk[3]);
        yo[1] = make_uint4(pk[4], pk[5], pk[6], pk[7]);
        yp += KFLAT;
    }
}

// ---------------------------------------------------------------------------
extern "C" void kernel_launch(void* const* d_in, const int* in_sizes, int n_in,
                              void* d_out, int out_size)
{
    const float* x      = (const float*)d_in[0];
    const float* loglam = (const float*)d_in[1];
    const float* Wd     = (const float*)d_in[2];
    const float* bd     = (const float*)d_in[3];
    const float* WB     = (const float*)d_in[4];
    const float* WC     = (const float*)d_in[5];
    const float* Wout   = (const float*)d_in[6];
    const float* bout   = (const float*)d_in[7];
    float* out          = (float*)d_out;

    float *p_delta, *p_Bt, *p_Ct, *p_hend, *p_D, *p_hstart;
    __half *p_xhi, *p_xlo, *p_Wd16, *p_Wouth, *p_flat;
    cudaGetSymbolAddress((void**)&p_delta,  g_delta);
    cudaGetSymbolAddress((void**)&p_Bt,     g_Bt);
    cudaGetSymbolAddress((void**)&p_Ct,     g_Ct);
    cudaGetSymbolAddress((void**)&p_hend,   g_hend);
    cudaGetSymbolAddress((void**)&p_D,      g_D);
    cudaGetSymbolAddress((void**)&p_hstart, g_hstart);
    cudaGetSymbolAddress((void**)&p_xhi,    g_xhi);
    cudaGetSymbolAddress((void**)&p_xlo,    g_xlo);
    cudaGetSymbolAddress((void**)&p_Wd16,   g_Wd16);
    cudaGetSymbolAddress((void**)&p_Wouth,  g_Wouth);
    cudaGetSymbolAddress((void**)&p_flat,   g_flat);

    cudaFuncSetAttribute(tgemm_d2,   cudaFuncAttributeMaxDynamicSharedMemorySize, D2_SMEM);
    cudaFuncSetAttribute(tgemm_fp16, cudaFuncAttributeMaxDynamicSharedMemorySize, TG2_SMEM);

    // splits / conversions
    {
        int n1 = MROWS * DMODEL;
        split_x16<<<(n1 + 255) / 256, 256>>>(x, p_xhi, p_xlo, n1);
        int n2 = DMODEL * DMODEL;
        to_fp16<<<(n2 + 255) / 256, 256>>>(Wd, p_Wd16, n2);
        int n3 = DMODEL * KFLAT;
        to_fp16<<<(n3 + 255) / 256, 256>>>(Wout, p_Wouth, n3);
    }

    // 1. delta = softplus(x @ Wd^T + bd)   [4096 x 768], fp16 2-term
    tgemm_d2<<<dim3(DMODEL / 96, MROWS / 128), 256, D2_SMEM>>>(
        p_xhi, p_xlo, p_Wd16, bd, p_delta, DMODEL, DMODEL);

    // 2. Bt, Ct
    bc_kernel<<<MROWS, 256>>>(x, WB, WC, p_Bt, p_Ct);

    // 3. segmented scan -> flat fp16 [4096 x 12288]
    scan_a<<<(BATCH * NSEG * DMODEL) / 256, 256>>>(p_delta, p_Bt, loglam,
                                                   p_hend, p_D);
    scan_b<<<(BATCH * DN) / 256, 256>>>(p_hend, p_D, p_hstart);
    scan_c<<<(BATCH * NSEG * DMODEL) / 256, 256>>>(p_delta, p_Bt, p_Ct, loglam,
                                                   p_hstart, p_flat);

    // 4. out = flat @ Wouth^T + bout   [4096 x 768], fp16 1-term
    tgemm_fp16<<<dim3(DMODEL / 96, MROWS / 128), 256, TG2_SMEM>>>(
        p_flat, p_Wouth, bout, out, DMODEL, KFLAT);
}